// round 9
// baseline (speedup 1.0000x reference)
#include <cuda_runtime.h>
#include <cuda_bf16.h>
#include <math.h>
#include <stdint.h>

// ---------------------------------------------------------------------------
// SpatialAttentionConv, R9: bf16 HMMA split-GEMMs, 1m x 8n warp layout
// (no B-fragment L2 redundancy), attention fused into out_gemm (g_o removed).
//
//   GEMM1: g_qkv(N x 384) = X @ ipw^T + ipb          (3 n-sections)
//   out_gemm: per-CTA attention (o into SMEM as split-bf16) then
//             out = O @ W2^T + X @ cw0^T + b2,  W2 = Cw1@Wo, b2 = Cw1@bo + cb
// Split trick: A = Ah + Al (bf16); A@W ~= Ah@Wh + Al@Wh + Ah@Wl (fp32 accum).
// ---------------------------------------------------------------------------

#define MAXN 200064

static __device__ float g_qkv[(size_t)MAXN * 384];
static __device__ float g_w2[128 * 128];
static __device__ float g_b2[128];
static __device__ uint4 g_bfm[8 * 64 * 32];   // B frags: [ks][ntile 0..63][lane]
                                              // ntile 0..47: ipw, 48..63: cw0
static __device__ uint4 g_bf2[8 * 16 * 32];   // W2 frags
static __device__ int g_is64;

// ------------------------------ helpers ------------------------------------
__device__ __forceinline__ uint32_t smem_u32(const void* p) {
    uint32_t a;
    asm("{ .reg .u64 t; cvta.to.shared.u64 t, %1; cvt.u32.u64 %0, t; }" : "=r"(a) : "l"(p));
    return a;
}
__device__ __forceinline__ uint32_t pk2(float a, float b) {
    __nv_bfloat162 t = __floats2bfloat162_rn(a, b);
    return *reinterpret_cast<uint32_t*>(&t);
}
__device__ __forceinline__ float bfl(float v) {   // v - bf16_round(v)
    return v - __bfloat162float(__float2bfloat16(v));
}

#define LDMATRIX_X4(r0, r1, r2, r3, addr) \
    asm volatile("ldmatrix.sync.aligned.m8n8.x4.shared.b16 {%0,%1,%2,%3}, [%4];" \
                 : "=r"(r0), "=r"(r1), "=r"(r2), "=r"(r3) : "r"(addr))

#define MMA16816(d, a, b0, b1) \
    asm volatile("mma.sync.aligned.m16n8k16.row.col.f32.bf16.bf16.f32 " \
                 "{%0,%1,%2,%3}, {%4,%5,%6,%7}, {%8,%9}, {%0,%1,%2,%3};" \
                 : "+f"((d)[0]), "+f"((d)[1]), "+f"((d)[2]), "+f"((d)[3]) \
                 : "r"((a)[0]), "r"((a)[1]), "r"((a)[2]), "r"((a)[3]), \
                   "r"(b0), "r"(b1))

#define ST_STRIDE 132               // staging row stride in floats (bank spread)
#define SMEM_BYTES (128 * ST_STRIDE * 4)   // 67584 >= 65536 tile bytes

// ------------------------------ small preps --------------------------------
__global__ void detect_kernel(const int* __restrict__ nbr32) {
    if (threadIdx.x == 0) {
        int any = 0;
        #pragma unroll 1
        for (int j = 1; j < 128; ++j) any |= nbr32[2 * j + 1];
        g_is64 = (any == 0) ? 1 : 0;
    }
}

__global__ void prep_w2_kernel(const float* __restrict__ conv_w,
                               const float* __restrict__ out_proj_w,
                               const float* __restrict__ out_proj_b,
                               const float* __restrict__ conv_b) {
    int n = blockIdx.x, i = threadIdx.x;
    float s = 0.f;
    #pragma unroll 4
    for (int m = 0; m < 128; ++m)
        s += conv_w[(n * 128 + m) * 2 + 1] * out_proj_w[m * 128 + i];
    g_w2[n * 128 + i] = s;
    if (i == 0) {
        float b = 0.f;
        for (int m = 0; m < 128; ++m)
            b += conv_w[(n * 128 + m) * 2 + 1] * out_proj_b[m];
        g_b2[n] = b + conv_b[n];
    }
}

// B fragments in mma register layout (m16n8k16.row.col):
//   reg0: B[k=(l%4)*2+{0,1},   n=l/4];  reg1: B[k=(l%4)*2+8+{0,1}, n=l/4]
// uint4 = {bh_reg0, bh_reg1, bl_reg0, bl_reg1}.
__global__ void prep_frag_mega(const float* __restrict__ ipw,
                               const float* __restrict__ cw) {
    int idx = blockIdx.x * blockDim.x + threadIdx.x;     // 16384
    int lane = idx & 31, t = (idx >> 5) & 63, ks = idx >> 11;
    int n = t * 8 + (lane >> 2);
    int k0 = ks * 16 + (lane & 3) * 2;
    float v[4];
    #pragma unroll
    for (int j = 0; j < 4; ++j) {
        int k = k0 + (j >> 1) * 8 + (j & 1);
        v[j] = (n < 384) ? ipw[n * 128 + k] : cw[((n - 384) * 128 + k) * 2];
    }
    uint4 o;
    o.x = pk2(v[0], v[1]);
    o.y = pk2(v[2], v[3]);
    o.z = pk2(bfl(v[0]), bfl(v[1]));
    o.w = pk2(bfl(v[2]), bfl(v[3]));
    g_bfm[idx] = o;
}

__global__ void prep_frag_w2() {
    int idx = blockIdx.x * blockDim.x + threadIdx.x;     // 4096
    int lane = idx & 31, t = (idx >> 5) & 15, ks = idx >> 9;
    int n = t * 8 + (lane >> 2);
    int k0 = ks * 16 + (lane & 3) * 2;
    float v[4];
    #pragma unroll
    for (int j = 0; j < 4; ++j)
        v[j] = g_w2[n * 128 + k0 + (j >> 1) * 8 + (j & 1)];
    uint4 o;
    o.x = pk2(v[0], v[1]);
    o.y = pk2(v[2], v[3]);
    o.z = pk2(bfl(v[0]), bfl(v[1]));
    o.w = pk2(bfl(v[2]), bfl(v[3]));
    g_bf2[idx] = o;
}

// ---------------------------------------------------------------------------
// Shared A tile: 128 rows x 128 bf16 (256B/row), hi at 0, lo at 32KB.
// 16B chunk (r, c) at r*256 + (c ^ (r & 7))*16 -> conflict-free ldmatrix.
// ---------------------------------------------------------------------------
__device__ __forceinline__ void fill_tile(const float* __restrict__ src,
                                          char* smem, int m0, int M, int tid) {
    #pragma unroll 1
    for (int i = tid; i < 2048; i += 256) {
        int r = i >> 4, c = i & 15;
        float4 v0 = make_float4(0.f, 0.f, 0.f, 0.f), v1 = v0;
        if (m0 + r < M) {
            const float* p = src + (size_t)(m0 + r) * 128 + c * 8;
            v0 = *(const float4*)p;
            v1 = *(const float4*)(p + 4);
        }
        uint4 hi, lo;
        hi.x = pk2(v0.x, v0.y); hi.y = pk2(v0.z, v0.w);
        hi.z = pk2(v1.x, v1.y); hi.w = pk2(v1.z, v1.w);
        lo.x = pk2(bfl(v0.x), bfl(v0.y)); lo.y = pk2(bfl(v0.z), bfl(v0.w));
        lo.z = pk2(bfl(v1.x), bfl(v1.y)); lo.w = pk2(bfl(v1.z), bfl(v1.w));
        uint32_t off = (uint32_t)(r * 256 + ((c ^ (r & 7)) << 4));
        *(uint4*)(smem + off) = hi;
        *(uint4*)(smem + 32768 + off) = lo;
    }
}

// MMA pass, 1m x 8n layout: warp wn owns cols [wn*16, wn*16+16) (2 ntiles),
// all 128 rows (8 mf), processed in two register halves of 4 mf.
// B fragments are read exactly once per CTA (no cross-warp redundancy).
__device__ __forceinline__ void mma_pass(uint32_t sb, const uint4* __restrict__ bfr,
                                         int ntb, int nstride, int lane,
                                         float acc[8][2][4]) {
    const int lr = lane & 15, lc = lane >> 4, ls = lane & 7;
    #pragma unroll 1
    for (int ks = 0; ks < 8; ++ks) {
        uint32_t ch = (uint32_t)((((ks * 2 + lc) ^ ls)) << 4);
        uint4 b0 = __ldg(&bfr[(ks * nstride + ntb) * 32 + lane]);
        uint4 b1 = __ldg(&bfr[(ks * nstride + ntb + 1) * 32 + lane]);
        #pragma unroll
        for (int h = 0; h < 2; ++h) {
            uint32_t ah[4][4], al[4][4];
            #pragma unroll
            for (int m4 = 0; m4 < 4; ++m4) {
                uint32_t ao = (uint32_t)((h * 64 + m4 * 16 + lr) * 256);
                LDMATRIX_X4(ah[m4][0], ah[m4][1], ah[m4][2], ah[m4][3],
                            sb + ao + ch);
                LDMATRIX_X4(al[m4][0], al[m4][1], al[m4][2], al[m4][3],
                            sb + 32768 + ao + ch);
            }
            #pragma unroll
            for (int m4 = 0; m4 < 4; ++m4) {
                int mf = h * 4 + m4;
                MMA16816(acc[mf][0], ah[m4], b0.x, b0.y);
                MMA16816(acc[mf][0], al[m4], b0.x, b0.y);
                MMA16816(acc[mf][0], ah[m4], b0.z, b0.w);
                MMA16816(acc[mf][1], ah[m4], b1.x, b1.y);
                MMA16816(acc[mf][1], al[m4], b1.x, b1.y);
                MMA16816(acc[mf][1], ah[m4], b1.z, b1.w);
            }
        }
    }
}

// Stage accumulators to padded SMEM (local 128x128 tile), 1m x 8n layout.
__device__ __forceinline__ void stage_acc(float* st, int wn, int lane,
                                          float acc[8][2][4]) {
    const int qrow = lane >> 2, qcol = (lane & 3) * 2;
    #pragma unroll
    for (int mf = 0; mf < 8; ++mf) {
        int r = mf * 16 + qrow;
        #pragma unroll
        for (int nf = 0; nf < 2; ++nf) {
            int c = wn * 16 + nf * 8 + qcol;
            st[r * ST_STRIDE + c]           = acc[mf][nf][0];
            st[r * ST_STRIDE + c + 1]       = acc[mf][nf][1];
            st[(r + 8) * ST_STRIDE + c]     = acc[mf][nf][2];
            st[(r + 8) * ST_STRIDE + c + 1] = acc[mf][nf][3];
        }
    }
}

// -------------------- GEMM1: QKV (3 sections of 128) -----------------------
// grid (3, tiles): sec n-fastest so the 3 secs of one m-tile share X via L2.
__global__ void __launch_bounds__(256, 2)
mega_gemm(const float* __restrict__ x, const float* __restrict__ ipb, int M) {
    extern __shared__ char smem[];
    const int tid = threadIdx.x;
    const int sec = blockIdx.x;
    const int m0 = blockIdx.y * 128;
    const int wn = tid >> 5, lane = tid & 31;

    fill_tile(x, smem, m0, M, tid);
    __syncthreads();

    float acc[8][2][4];
    #pragma unroll
    for (int mf = 0; mf < 8; ++mf)
        #pragma unroll
        for (int nf = 0; nf < 2; ++nf)
            #pragma unroll
            for (int q = 0; q < 4; ++q) acc[mf][nf][q] = 0.f;

    mma_pass(smem_u32(smem), g_bfm, sec * 16 + wn * 2, 64, lane, acc);

    // Staged, coalesced epilogue.
    __syncthreads();
    float* st = (float*)smem;
    stage_acc(st, wn, lane, acc);
    __syncthreads();

    #pragma unroll 1
    for (int i = tid; i < 4096; i += 256) {
        int r = i >> 5, c = (i & 31) << 2;
        if (m0 + r < M) {
            float4 v = *(const float4*)&st[r * ST_STRIDE + c];
            float4 b = *(const float4*)(ipb + sec * 128 + c);
            v.x += b.x; v.y += b.y; v.z += b.z; v.w += b.w;
            *(float4*)(g_qkv + (size_t)(m0 + r) * 384 + sec * 128 + c) = v;
        }
    }
}

// ------------- out_gemm: fused attention + O@W2^T + X@cw0^T + b2 -----------
// Phase A: each warp computes attention o for 16 faces of this CTA's tile,
// writing split-bf16 directly into the swizzled A tile (no g_o roundtrip).
// Phase B: o @ W2^T. Phase C: X @ cw0^T. Epilogue staged + coalesced.
__global__ void __launch_bounds__(256, 2)
out_gemm(const float* __restrict__ x, const void* __restrict__ nbr,
         float* __restrict__ out, int M) {
    extern __shared__ char smem[];
    const int tid = threadIdx.x;
    const int m0 = blockIdx.x * 128;
    const int wn = tid >> 5, lane = tid & 31;
    const float* __restrict__ qkv = g_qkv;
    const int is64 = g_is64;

    // ---- Phase A: attention for faces m0 + wn*16 + [0,16) ----
    #pragma unroll 1
    for (int f = 0; f < 16; ++f) {
        const int r = wn * 16 + f;             // tile-local row
        const int face = m0 + r;
        float4 oa = make_float4(0.f, 0.f, 0.f, 0.f);
        if (face < M) {
            const float4 q = *(const float4*)&qkv[(size_t)face * 384 + lane * 4];
            int myj = 0;
            if (lane < 8) {
                if (is64) myj = (int)((const long long*)nbr)[(size_t)face * 9 + 1 + lane];
                else      myj = ((const int*)nbr)[(size_t)face * 9 + 1 + lane];
            }
            float  sc[8];
            float4 vv[8];
            const float scale = 0.17677669529663687f;   // 1/sqrt(32)
            #pragma unroll
            for (int kk = 0; kk < 8; ++kk) {
                int j = __shfl_sync(0xffffffffu, myj, kk);
                float s;
                float4 v;
                if (j < M) {
                    const float* base = &qkv[(size_t)j * 384 + 128 + lane * 4];
                    float4 kf = *(const float4*)base;
                    v = *(const float4*)(base + 128);
                    float p = q.x * kf.x + q.y * kf.y + q.z * kf.z + q.w * kf.w;
                    p += __shfl_xor_sync(0xffffffffu, p, 1);
                    p += __shfl_xor_sync(0xffffffffu, p, 2);
                    p += __shfl_xor_sync(0xffffffffu, p, 4);
                    s = p * scale;
                } else {
                    s = -INFINITY;
                    v = make_float4(0.f, 0.f, 0.f, 0.f);
                }
                sc[kk] = s;
                vv[kk] = v;
            }
            float mx = sc[0];
            #pragma unroll
            for (int kk = 1; kk < 8; ++kk) mx = fmaxf(mx, sc[kk]);
            float den = 0.f;
            #pragma unroll
            for (int kk = 0; kk < 8; ++kk) { float e = __expf(sc[kk] - mx); sc[kk] = e; den += e; }
            const float inv = 1.0f / den;
            #pragma unroll
            for (int kk = 0; kk < 8; ++kk) {
                oa.x += sc[kk] * vv[kk].x;
                oa.y += sc[kk] * vv[kk].y;
                oa.z += sc[kk] * vv[kk].z;
                oa.w += sc[kk] * vv[kk].w;
            }
            oa.x *= inv; oa.y *= inv; oa.z *= inv; oa.w *= inv;
        }
        // Write split-bf16 into swizzled tile: lane owns channels 4l..4l+3,
        // i.e. half of 16B chunk c = lane>>1, byte half (lane&1)*8.
        uint32_t off = (uint32_t)(r * 256 + ((((uint32_t)lane >> 1) ^ (r & 7)) << 4)
                                  + (lane & 1) * 8);
        uint2 hi = make_uint2(pk2(oa.x, oa.y), pk2(oa.z, oa.w));
        uint2 lo = make_uint2(pk2(bfl(oa.x), bfl(oa.y)), pk2(bfl(oa.z), bfl(oa.w)));
        *(uint2*)(smem + off) = hi;
        *(uint2*)(smem + 32768 + off) = lo;
    }
    __syncthreads();

    float acc[8][2][4];
    #pragma unroll
    for (int mf = 0; mf < 8; ++mf)
        #pragma unroll
        for (int nf = 0; nf < 2; ++nf)
            #pragma unroll
            for (int q = 0; q < 4; ++q) acc[mf][nf][q] = 0.f;

    // ---- Phase B: O @ W2^T ----
    mma_pass(smem_u32(smem), g_bf2, wn * 2, 16, lane, acc);
    __syncthreads();

    // ---- Phase C: X @ cw0^T (cw0 = ntiles 48..63 of g_bfm) ----
    fill_tile(x, smem, m0, M, tid);
    __syncthreads();
    mma_pass(smem_u32(smem), g_bfm, 48 + wn * 2, 64, lane, acc);

    // ---- Epilogue ----
    __syncthreads();
    float* st = (float*)smem;
    stage_acc(st, wn, lane, acc);
    __syncthreads();

    #pragma unroll 1
    for (int i = tid; i < 4096; i += 256) {
        int r = i >> 5, c = (i & 31) << 2;
        if (m0 + r < M) {
            float4 v = *(const float4*)&st[r * ST_STRIDE + c];
            float4 b = *(const float4*)(g_b2 + c);
            v.x += b.x; v.y += b.y; v.z += b.z; v.w += b.w;
            *(float4*)(out + (size_t)(m0 + r) * 128 + c) = v;
        }
    }
}

// ------------------------------ launch -------------------------------------
extern "C" void kernel_launch(void* const* d_in, const int* in_sizes, int n_in,
                              void* d_out, int out_size) {
    const float* x   = (const float*)d_in[0];
    const void*  nbr = d_in[1];
    const float* ipw = (const float*)d_in[4];
    const float* ipb = (const float*)d_in[5];
    const float* opw = (const float*)d_in[6];
    const float* opb = (const float*)d_in[7];
    const float* cw  = (const float*)d_in[8];
    const float* cb  = (const float*)d_in[9];
    const int N = in_sizes[0] / 128;
    float* out = (float*)d_out;

    cudaFuncSetAttribute(mega_gemm, cudaFuncAttributeMaxDynamicSharedMemorySize, SMEM_BYTES);
    cudaFuncSetAttribute(out_gemm, cudaFuncAttributeMaxDynamicSharedMemorySize, SMEM_BYTES);

    const int tiles = (N + 127) / 128;

    detect_kernel<<<1, 32>>>((const int*)nbr);
    prep_w2_kernel<<<128, 128>>>(cw, opw, opb, cb);
    prep_frag_mega<<<64, 256>>>(ipw, cw);
    prep_frag_w2<<<16, 256>>>();

    dim3 g1(3, tiles);
    mega_gemm<<<g1, 256, SMEM_BYTES>>>(x, ipb, N);
    out_gemm<<<tiles, 256, SMEM_BYTES>>>(x, nbr, out, N);
}

// round 10
// speedup vs baseline: 1.2664x; 1.2664x over previous
#include <cuda_runtime.h>
#include <cuda_bf16.h>
#include <math.h>
#include <stdint.h>

// ---------------------------------------------------------------------------
// SpatialAttentionConv, R10: R8 structure (standalone attention, g_o buffer)
// with ONLY the 1m x 8n GEMM warp layout applied (B frags read once per CTA).
//
//   GEMM1: g_qkv(N x 384) = X @ ipw^T + ipb          (3 n-sections)
//   attn : per-face 8-neighbor masked softmax, fp32 (separate kernel)
//   GEMM2: out = O @ W2^T + X @ cw0^T + b2,  W2 = Cw1@Wo, b2 = Cw1@bo + cb
// Split trick: A = Ah + Al (bf16); A@W ~= Ah@Wh + Al@Wh + Ah@Wl (fp32 accum).
// ---------------------------------------------------------------------------

#define MAXN 200064

static __device__ float g_qkv[(size_t)MAXN * 384];
static __device__ float g_o[(size_t)MAXN * 128];
static __device__ float g_w2[128 * 128];
static __device__ float g_b2[128];
static __device__ uint4 g_bfm[8 * 64 * 32];   // B frags: [ks][ntile 0..63][lane]
                                              // ntile 0..47: ipw, 48..63: cw0
static __device__ uint4 g_bf2[8 * 16 * 32];   // W2 frags
static __device__ int g_is64;

// ------------------------------ helpers ------------------------------------
__device__ __forceinline__ uint32_t smem_u32(const void* p) {
    uint32_t a;
    asm("{ .reg .u64 t; cvta.to.shared.u64 t, %1; cvt.u32.u64 %0, t; }" : "=r"(a) : "l"(p));
    return a;
}
__device__ __forceinline__ uint32_t pk2(float a, float b) {
    __nv_bfloat162 t = __floats2bfloat162_rn(a, b);
    return *reinterpret_cast<uint32_t*>(&t);
}
__device__ __forceinline__ float bfl(float v) {   // v - bf16_round(v)
    return v - __bfloat162float(__float2bfloat16(v));
}

#define LDMATRIX_X4(r0, r1, r2, r3, addr) \
    asm volatile("ldmatrix.sync.aligned.m8n8.x4.shared.b16 {%0,%1,%2,%3}, [%4];" \
                 : "=r"(r0), "=r"(r1), "=r"(r2), "=r"(r3) : "r"(addr))

#define MMA16816(d, a, b0, b1) \
    asm volatile("mma.sync.aligned.m16n8k16.row.col.f32.bf16.bf16.f32 " \
                 "{%0,%1,%2,%3}, {%4,%5,%6,%7}, {%8,%9}, {%0,%1,%2,%3};" \
                 : "+f"((d)[0]), "+f"((d)[1]), "+f"((d)[2]), "+f"((d)[3]) \
                 : "r"((a)[0]), "r"((a)[1]), "r"((a)[2]), "r"((a)[3]), \
                   "r"(b0), "r"(b1))

#define ST_STRIDE 132               // staging row stride in floats (bank spread)
#define SMEM_BYTES (128 * ST_STRIDE * 4)   // 67584 >= 65536 tile bytes

// ------------------------------ small preps --------------------------------
__global__ void detect_kernel(const int* __restrict__ nbr32) {
    if (threadIdx.x == 0) {
        int any = 0;
        #pragma unroll 1
        for (int j = 1; j < 128; ++j) any |= nbr32[2 * j + 1];
        g_is64 = (any == 0) ? 1 : 0;
    }
}

__global__ void prep_w2_kernel(const float* __restrict__ conv_w,
                               const float* __restrict__ out_proj_w,
                               const float* __restrict__ out_proj_b,
                               const float* __restrict__ conv_b) {
    int n = blockIdx.x, i = threadIdx.x;
    float s = 0.f;
    #pragma unroll 4
    for (int m = 0; m < 128; ++m)
        s += conv_w[(n * 128 + m) * 2 + 1] * out_proj_w[m * 128 + i];
    g_w2[n * 128 + i] = s;
    if (i == 0) {
        float b = 0.f;
        for (int m = 0; m < 128; ++m)
            b += conv_w[(n * 128 + m) * 2 + 1] * out_proj_b[m];
        g_b2[n] = b + conv_b[n];
    }
}

// B fragments in mma register layout (m16n8k16.row.col):
//   reg0: B[k=(l%4)*2+{0,1},   n=l/4];  reg1: B[k=(l%4)*2+8+{0,1}, n=l/4]
// uint4 = {bh_reg0, bh_reg1, bl_reg0, bl_reg1}.
__global__ void prep_frag_mega(const float* __restrict__ ipw,
                               const float* __restrict__ cw) {
    int idx = blockIdx.x * blockDim.x + threadIdx.x;     // 16384
    int lane = idx & 31, t = (idx >> 5) & 63, ks = idx >> 11;
    int n = t * 8 + (lane >> 2);
    int k0 = ks * 16 + (lane & 3) * 2;
    float v[4];
    #pragma unroll
    for (int j = 0; j < 4; ++j) {
        int k = k0 + (j >> 1) * 8 + (j & 1);
        v[j] = (n < 384) ? ipw[n * 128 + k] : cw[((n - 384) * 128 + k) * 2];
    }
    uint4 o;
    o.x = pk2(v[0], v[1]);
    o.y = pk2(v[2], v[3]);
    o.z = pk2(bfl(v[0]), bfl(v[1]));
    o.w = pk2(bfl(v[2]), bfl(v[3]));
    g_bfm[idx] = o;
}

__global__ void prep_frag_w2() {
    int idx = blockIdx.x * blockDim.x + threadIdx.x;     // 4096
    int lane = idx & 31, t = (idx >> 5) & 15, ks = idx >> 9;
    int n = t * 8 + (lane >> 2);
    int k0 = ks * 16 + (lane & 3) * 2;
    float v[4];
    #pragma unroll
    for (int j = 0; j < 4; ++j)
        v[j] = g_w2[n * 128 + k0 + (j >> 1) * 8 + (j & 1)];
    uint4 o;
    o.x = pk2(v[0], v[1]);
    o.y = pk2(v[2], v[3]);
    o.z = pk2(bfl(v[0]), bfl(v[1]));
    o.w = pk2(bfl(v[2]), bfl(v[3]));
    g_bf2[idx] = o;
}

// ---------------------------------------------------------------------------
// Shared A tile: 128 rows x 128 bf16 (256B/row), hi at 0, lo at 32KB.
// 16B chunk (r, c) at r*256 + (c ^ (r & 7))*16 -> conflict-free ldmatrix.
// ---------------------------------------------------------------------------
__device__ __forceinline__ void fill_tile(const float* __restrict__ src,
                                          char* smem, int m0, int M, int tid) {
    #pragma unroll 1
    for (int i = tid; i < 2048; i += 256) {
        int r = i >> 4, c = i & 15;
        float4 v0 = make_float4(0.f, 0.f, 0.f, 0.f), v1 = v0;
        if (m0 + r < M) {
            const float* p = src + (size_t)(m0 + r) * 128 + c * 8;
            v0 = *(const float4*)p;
            v1 = *(const float4*)(p + 4);
        }
        uint4 hi, lo;
        hi.x = pk2(v0.x, v0.y); hi.y = pk2(v0.z, v0.w);
        hi.z = pk2(v1.x, v1.y); hi.w = pk2(v1.z, v1.w);
        lo.x = pk2(bfl(v0.x), bfl(v0.y)); lo.y = pk2(bfl(v0.z), bfl(v0.w));
        lo.z = pk2(bfl(v1.x), bfl(v1.y)); lo.w = pk2(bfl(v1.z), bfl(v1.w));
        uint32_t off = (uint32_t)(r * 256 + ((c ^ (r & 7)) << 4));
        *(uint4*)(smem + off) = hi;
        *(uint4*)(smem + 32768 + off) = lo;
    }
}

// MMA pass, 1m x 8n layout: warp wn owns cols [wn*16, wn*16+16) (2 ntiles),
// all 128 rows (8 mf), processed in two register halves of 4 mf.
// B fragments are read exactly once per CTA (no cross-warp redundancy).
__device__ __forceinline__ void mma_pass(uint32_t sb, const uint4* __restrict__ bfr,
                                         int ntb, int nstride, int lane,
                                         float acc[8][2][4]) {
    const int lr = lane & 15, lc = lane >> 4, ls = lane & 7;
    #pragma unroll 1
    for (int ks = 0; ks < 8; ++ks) {
        uint32_t ch = (uint32_t)((((ks * 2 + lc) ^ ls)) << 4);
        uint4 b0 = __ldg(&bfr[(ks * nstride + ntb) * 32 + lane]);
        uint4 b1 = __ldg(&bfr[(ks * nstride + ntb + 1) * 32 + lane]);
        #pragma unroll
        for (int h = 0; h < 2; ++h) {
            uint32_t ah[4][4], al[4][4];
            #pragma unroll
            for (int m4 = 0; m4 < 4; ++m4) {
                uint32_t ao = (uint32_t)((h * 64 + m4 * 16 + lr) * 256);
                LDMATRIX_X4(ah[m4][0], ah[m4][1], ah[m4][2], ah[m4][3],
                            sb + ao + ch);
                LDMATRIX_X4(al[m4][0], al[m4][1], al[m4][2], al[m4][3],
                            sb + 32768 + ao + ch);
            }
            #pragma unroll
            for (int m4 = 0; m4 < 4; ++m4) {
                int mf = h * 4 + m4;
                MMA16816(acc[mf][0], ah[m4], b0.x, b0.y);
                MMA16816(acc[mf][0], al[m4], b0.x, b0.y);
                MMA16816(acc[mf][0], ah[m4], b0.z, b0.w);
                MMA16816(acc[mf][1], ah[m4], b1.x, b1.y);
                MMA16816(acc[mf][1], al[m4], b1.x, b1.y);
                MMA16816(acc[mf][1], ah[m4], b1.z, b1.w);
            }
        }
    }
}

// Stage accumulators to padded SMEM (local 128x128 tile), 1m x 8n layout.
__device__ __forceinline__ void stage_acc(float* st, int wn, int lane,
                                          float acc[8][2][4]) {
    const int qrow = lane >> 2, qcol = (lane & 3) * 2;
    #pragma unroll
    for (int mf = 0; mf < 8; ++mf) {
        int r = mf * 16 + qrow;
        #pragma unroll
        for (int nf = 0; nf < 2; ++nf) {
            int c = wn * 16 + nf * 8 + qcol;
            st[r * ST_STRIDE + c]           = acc[mf][nf][0];
            st[r * ST_STRIDE + c + 1]       = acc[mf][nf][1];
            st[(r + 8) * ST_STRIDE + c]     = acc[mf][nf][2];
            st[(r + 8) * ST_STRIDE + c + 1] = acc[mf][nf][3];
        }
    }
}

// -------------------- GEMM1: QKV (3 sections of 128) -----------------------
// grid (3, tiles): sec n-fastest so the 3 secs of one m-tile share X via L2.
__global__ void __launch_bounds__(256, 2)
mega_gemm(const float* __restrict__ x, const float* __restrict__ ipb, int M) {
    extern __shared__ char smem[];
    const int tid = threadIdx.x;
    const int sec = blockIdx.x;
    const int m0 = blockIdx.y * 128;
    const int wn = tid >> 5, lane = tid & 31;

    fill_tile(x, smem, m0, M, tid);
    __syncthreads();

    float acc[8][2][4];
    #pragma unroll
    for (int mf = 0; mf < 8; ++mf)
        #pragma unroll
        for (int nf = 0; nf < 2; ++nf)
            #pragma unroll
            for (int q = 0; q < 4; ++q) acc[mf][nf][q] = 0.f;

    mma_pass(smem_u32(smem), g_bfm, sec * 16 + wn * 2, 64, lane, acc);

    // Staged, coalesced epilogue.
    __syncthreads();
    float* st = (float*)smem;
    stage_acc(st, wn, lane, acc);
    __syncthreads();

    #pragma unroll 1
    for (int i = tid; i < 4096; i += 256) {
        int r = i >> 5, c = (i & 31) << 2;
        if (m0 + r < M) {
            float4 v = *(const float4*)&st[r * ST_STRIDE + c];
            float4 b = *(const float4*)(ipb + sec * 128 + c);
            v.x += b.x; v.y += b.y; v.z += b.z; v.w += b.w;
            *(float4*)(g_qkv + (size_t)(m0 + r) * 384 + sec * 128 + c) = v;
        }
    }
}

// -------------------- GEMM2: out = O@W2^T + X@cw0^T + b2 -------------------
__global__ void __launch_bounds__(256, 2)
out_gemm(const float* __restrict__ x, float* __restrict__ out, int M) {
    extern __shared__ char smem[];
    const int tid = threadIdx.x;
    const int m0 = blockIdx.x * 128;
    const int wn = tid >> 5, lane = tid & 31;

    float acc[8][2][4];
    #pragma unroll
    for (int mf = 0; mf < 8; ++mf)
        #pragma unroll
        for (int nf = 0; nf < 2; ++nf)
            #pragma unroll
            for (int q = 0; q < 4; ++q) acc[mf][nf][q] = 0.f;

    // Pass 1: O @ W2^T
    fill_tile(g_o, smem, m0, M, tid);
    __syncthreads();
    mma_pass(smem_u32(smem), g_bf2, wn * 2, 16, lane, acc);
    __syncthreads();

    // Pass 2: X @ cw0^T (cw0 = ntiles 48..63 of g_bfm)
    fill_tile(x, smem, m0, M, tid);
    __syncthreads();
    mma_pass(smem_u32(smem), g_bfm, 48 + wn * 2, 64, lane, acc);

    // Staged, coalesced epilogue.
    __syncthreads();
    float* st = (float*)smem;
    stage_acc(st, wn, lane, acc);
    __syncthreads();

    #pragma unroll 1
    for (int i = tid; i < 4096; i += 256) {
        int r = i >> 5, c = (i & 31) << 2;
        if (m0 + r < M) {
            float4 v = *(const float4*)&st[r * ST_STRIDE + c];
            float4 b = *(const float4*)(g_b2 + c);
            v.x += b.x; v.y += b.y; v.z += b.z; v.w += b.w;
            *(float4*)(out + (size_t)(m0 + r) * 128 + c) = v;
        }
    }
}

// ------------------------------ attention ----------------------------------
__global__ void __launch_bounds__(256)
attn_kernel(const void* __restrict__ nbr, int N) {
    const int lane = threadIdx.x & 31;
    const int face = blockIdx.x * (blockDim.x >> 5) + (threadIdx.x >> 5);
    if (face >= N) return;

    const float* __restrict__ qkv = g_qkv;
    const float4 q = *(const float4*)&qkv[(size_t)face * 384 + lane * 4];

    int myj = 0;
    if (lane < 8) {
        if (g_is64) myj = (int)((const long long*)nbr)[(size_t)face * 9 + 1 + lane];
        else        myj = ((const int*)nbr)[(size_t)face * 9 + 1 + lane];
    }

    float  sc[8];
    float4 vv[8];
    const float scale = 0.17677669529663687f;  // 1/sqrt(32)

    #pragma unroll
    for (int kk = 0; kk < 8; ++kk) {
        int j = __shfl_sync(0xffffffffu, myj, kk);
        float s;
        float4 v;
        if (j < N) {
            const float* base = &qkv[(size_t)j * 384 + 128 + lane * 4];
            float4 kf = *(const float4*)base;
            v = *(const float4*)(base + 128);
            float p = q.x * kf.x + q.y * kf.y + q.z * kf.z + q.w * kf.w;
            p += __shfl_xor_sync(0xffffffffu, p, 1);
            p += __shfl_xor_sync(0xffffffffu, p, 2);
            p += __shfl_xor_sync(0xffffffffu, p, 4);
            s = p * scale;
        } else {
            s = -INFINITY;
            v = make_float4(0.f, 0.f, 0.f, 0.f);
        }
        sc[kk] = s;
        vv[kk] = v;
    }

    float m = sc[0];
    #pragma unroll
    for (int kk = 1; kk < 8; ++kk) m = fmaxf(m, sc[kk]);
    float den = 0.f;
    #pragma unroll
    for (int kk = 0; kk < 8; ++kk) { float e = __expf(sc[kk] - m); sc[kk] = e; den += e; }
    const float inv = 1.0f / den;

    float4 acc = make_float4(0.f, 0.f, 0.f, 0.f);
    #pragma unroll
    for (int kk = 0; kk < 8; ++kk) {
        acc.x += sc[kk] * vv[kk].x;
        acc.y += sc[kk] * vv[kk].y;
        acc.z += sc[kk] * vv[kk].z;
        acc.w += sc[kk] * vv[kk].w;
    }
    acc.x *= inv; acc.y *= inv; acc.z *= inv; acc.w *= inv;

    *(float4*)&g_o[(size_t)face * 128 + lane * 4] = acc;
}

// ------------------------------ launch -------------------------------------
extern "C" void kernel_launch(void* const* d_in, const int* in_sizes, int n_in,
                              void* d_out, int out_size) {
    const float* x   = (const float*)d_in[0];
    const void*  nbr = d_in[1];
    const float* ipw = (const float*)d_in[4];
    const float* ipb = (const float*)d_in[5];
    const float* opw = (const float*)d_in[6];
    const float* opb = (const float*)d_in[7];
    const float* cw  = (const float*)d_in[8];
    const float* cb  = (const float*)d_in[9];
    const int N = in_sizes[0] / 128;
    float* out = (float*)d_out;

    cudaFuncSetAttribute(mega_gemm, cudaFuncAttributeMaxDynamicSharedMemorySize, SMEM_BYTES);
    cudaFuncSetAttribute(out_gemm, cudaFuncAttributeMaxDynamicSharedMemorySize, SMEM_BYTES);

    const int tiles = (N + 127) / 128;

    detect_kernel<<<1, 32>>>((const int*)nbr);
    prep_w2_kernel<<<128, 128>>>(cw, opw, opb, cb);
    prep_frag_mega<<<64, 256>>>(ipw, cw);
    prep_frag_w2<<<16, 256>>>();

    dim3 g1(3, tiles);
    mega_gemm<<<g1, 256, SMEM_BYTES>>>(x, ipb, N);
    attn_kernel<<<(N + 7) / 8, 256>>>(nbr, N);
    out_gemm<<<tiles, 256, SMEM_BYTES>>>(x, out, N);
}

// round 11
// speedup vs baseline: 1.4067x; 1.1108x over previous
#include <cuda_runtime.h>
#include <cuda_bf16.h>
#include <math.h>
#include <stdint.h>

// ---------------------------------------------------------------------------
// SpatialAttentionConv, R11: R10 + streaming-softmax attention (low regs ->
// high occupancy) + launch order shuffled so ncu's fixed skip window lands on
// mega_gemm instead of a prep kernel.
//
//   GEMM1: g_qkv(N x 384) = X @ ipw^T + ipb          (3 n-sections)
//   attn : per-face 8-neighbor masked ONLINE softmax, fp32
//   GEMM2: out = O @ W2^T + X @ cw0^T + b2,  W2 = Cw1@Wo, b2 = Cw1@bo + cb
// Split trick: A = Ah + Al (bf16); A@W ~= Ah@Wh + Al@Wh + Ah@Wl (fp32 accum).
// ---------------------------------------------------------------------------

#define MAXN 200064

static __device__ float g_qkv[(size_t)MAXN * 384];
static __device__ float g_o[(size_t)MAXN * 128];
static __device__ float g_w2[128 * 128];
static __device__ float g_b2[128];
static __device__ uint4 g_bfm[8 * 64 * 32];   // B frags: [ks][ntile 0..63][lane]
                                              // ntile 0..47: ipw, 48..63: cw0
static __device__ uint4 g_bf2[8 * 16 * 32];   // W2 frags
static __device__ int g_is64;

// ------------------------------ helpers ------------------------------------
__device__ __forceinline__ uint32_t smem_u32(const void* p) {
    uint32_t a;
    asm("{ .reg .u64 t; cvta.to.shared.u64 t, %1; cvt.u32.u64 %0, t; }" : "=r"(a) : "l"(p));
    return a;
}
__device__ __forceinline__ uint32_t pk2(float a, float b) {
    __nv_bfloat162 t = __floats2bfloat162_rn(a, b);
    return *reinterpret_cast<uint32_t*>(&t);
}
__device__ __forceinline__ float bfl(float v) {   // v - bf16_round(v)
    return v - __bfloat162float(__float2bfloat16(v));
}

#define LDMATRIX_X4(r0, r1, r2, r3, addr) \
    asm volatile("ldmatrix.sync.aligned.m8n8.x4.shared.b16 {%0,%1,%2,%3}, [%4];" \
                 : "=r"(r0), "=r"(r1), "=r"(r2), "=r"(r3) : "r"(addr))

#define MMA16816(d, a, b0, b1) \
    asm volatile("mma.sync.aligned.m16n8k16.row.col.f32.bf16.bf16.f32 " \
                 "{%0,%1,%2,%3}, {%4,%5,%6,%7}, {%8,%9}, {%0,%1,%2,%3};" \
                 : "+f"((d)[0]), "+f"((d)[1]), "+f"((d)[2]), "+f"((d)[3]) \
                 : "r"((a)[0]), "r"((a)[1]), "r"((a)[2]), "r"((a)[3]), \
                   "r"(b0), "r"(b1))

#define ST_STRIDE 132               // staging row stride in floats (bank spread)
#define SMEM_BYTES (128 * ST_STRIDE * 4)   // 67584 >= 65536 tile bytes

// ------------------------------ small preps --------------------------------
__global__ void detect_kernel(const int* __restrict__ nbr32) {
    if (threadIdx.x == 0) {
        int any = 0;
        #pragma unroll 1
        for (int j = 1; j < 128; ++j) any |= nbr32[2 * j + 1];
        g_is64 = (any == 0) ? 1 : 0;
    }
}

__global__ void prep_w2_kernel(const float* __restrict__ conv_w,
                               const float* __restrict__ out_proj_w,
                               const float* __restrict__ out_proj_b,
                               const float* __restrict__ conv_b) {
    int n = blockIdx.x, i = threadIdx.x;
    float s = 0.f;
    #pragma unroll 4
    for (int m = 0; m < 128; ++m)
        s += conv_w[(n * 128 + m) * 2 + 1] * out_proj_w[m * 128 + i];
    g_w2[n * 128 + i] = s;
    if (i == 0) {
        float b = 0.f;
        for (int m = 0; m < 128; ++m)
            b += conv_w[(n * 128 + m) * 2 + 1] * out_proj_b[m];
        g_b2[n] = b + conv_b[n];
    }
}

// B fragments in mma register layout (m16n8k16.row.col):
//   reg0: B[k=(l%4)*2+{0,1},   n=l/4];  reg1: B[k=(l%4)*2+8+{0,1}, n=l/4]
// uint4 = {bh_reg0, bh_reg1, bl_reg0, bl_reg1}.
__global__ void prep_frag_mega(const float* __restrict__ ipw,
                               const float* __restrict__ cw) {
    int idx = blockIdx.x * blockDim.x + threadIdx.x;     // 16384
    int lane = idx & 31, t = (idx >> 5) & 63, ks = idx >> 11;
    int n = t * 8 + (lane >> 2);
    int k0 = ks * 16 + (lane & 3) * 2;
    float v[4];
    #pragma unroll
    for (int j = 0; j < 4; ++j) {
        int k = k0 + (j >> 1) * 8 + (j & 1);
        v[j] = (n < 384) ? ipw[n * 128 + k] : cw[((n - 384) * 128 + k) * 2];
    }
    uint4 o;
    o.x = pk2(v[0], v[1]);
    o.y = pk2(v[2], v[3]);
    o.z = pk2(bfl(v[0]), bfl(v[1]));
    o.w = pk2(bfl(v[2]), bfl(v[3]));
    g_bfm[idx] = o;
}

__global__ void prep_frag_w2() {
    int idx = blockIdx.x * blockDim.x + threadIdx.x;     // 4096
    int lane = idx & 31, t = (idx >> 5) & 15, ks = idx >> 9;
    int n = t * 8 + (lane >> 2);
    int k0 = ks * 16 + (lane & 3) * 2;
    float v[4];
    #pragma unroll
    for (int j = 0; j < 4; ++j)
        v[j] = g_w2[n * 128 + k0 + (j >> 1) * 8 + (j & 1)];
    uint4 o;
    o.x = pk2(v[0], v[1]);
    o.y = pk2(v[2], v[3]);
    o.z = pk2(bfl(v[0]), bfl(v[1]));
    o.w = pk2(bfl(v[2]), bfl(v[3]));
    g_bf2[idx] = o;
}

// ---------------------------------------------------------------------------
// Shared A tile: 128 rows x 128 bf16 (256B/row), hi at 0, lo at 32KB.
// 16B chunk (r, c) at r*256 + (c ^ (r & 7))*16 -> conflict-free ldmatrix.
// ---------------------------------------------------------------------------
__device__ __forceinline__ void fill_tile(const float* __restrict__ src,
                                          char* smem, int m0, int M, int tid) {
    #pragma unroll 1
    for (int i = tid; i < 2048; i += 256) {
        int r = i >> 4, c = i & 15;
        float4 v0 = make_float4(0.f, 0.f, 0.f, 0.f), v1 = v0;
        if (m0 + r < M) {
            const float* p = src + (size_t)(m0 + r) * 128 + c * 8;
            v0 = *(const float4*)p;
            v1 = *(const float4*)(p + 4);
        }
        uint4 hi, lo;
        hi.x = pk2(v0.x, v0.y); hi.y = pk2(v0.z, v0.w);
        hi.z = pk2(v1.x, v1.y); hi.w = pk2(v1.z, v1.w);
        lo.x = pk2(bfl(v0.x), bfl(v0.y)); lo.y = pk2(bfl(v0.z), bfl(v0.w));
        lo.z = pk2(bfl(v1.x), bfl(v1.y)); lo.w = pk2(bfl(v1.z), bfl(v1.w));
        uint32_t off = (uint32_t)(r * 256 + ((c ^ (r & 7)) << 4));
        *(uint4*)(smem + off) = hi;
        *(uint4*)(smem + 32768 + off) = lo;
    }
}

// MMA pass, 1m x 8n layout: warp wn owns cols [wn*16, wn*16+16) (2 ntiles),
// all 128 rows (8 mf), processed in two register halves of 4 mf.
__device__ __forceinline__ void mma_pass(uint32_t sb, const uint4* __restrict__ bfr,
                                         int ntb, int nstride, int lane,
                                         float acc[8][2][4]) {
    const int lr = lane & 15, lc = lane >> 4, ls = lane & 7;
    #pragma unroll 1
    for (int ks = 0; ks < 8; ++ks) {
        uint32_t ch = (uint32_t)((((ks * 2 + lc) ^ ls)) << 4);
        uint4 b0 = __ldg(&bfr[(ks * nstride + ntb) * 32 + lane]);
        uint4 b1 = __ldg(&bfr[(ks * nstride + ntb + 1) * 32 + lane]);
        #pragma unroll
        for (int h = 0; h < 2; ++h) {
            uint32_t ah[4][4], al[4][4];
            #pragma unroll
            for (int m4 = 0; m4 < 4; ++m4) {
                uint32_t ao = (uint32_t)((h * 64 + m4 * 16 + lr) * 256);
                LDMATRIX_X4(ah[m4][0], ah[m4][1], ah[m4][2], ah[m4][3],
                            sb + ao + ch);
                LDMATRIX_X4(al[m4][0], al[m4][1], al[m4][2], al[m4][3],
                            sb + 32768 + ao + ch);
            }
            #pragma unroll
            for (int m4 = 0; m4 < 4; ++m4) {
                int mf = h * 4 + m4;
                MMA16816(acc[mf][0], ah[m4], b0.x, b0.y);
                MMA16816(acc[mf][0], al[m4], b0.x, b0.y);
                MMA16816(acc[mf][0], ah[m4], b0.z, b0.w);
                MMA16816(acc[mf][1], ah[m4], b1.x, b1.y);
                MMA16816(acc[mf][1], al[m4], b1.x, b1.y);
                MMA16816(acc[mf][1], ah[m4], b1.z, b1.w);
            }
        }
    }
}

// Stage accumulators to padded SMEM (local 128x128 tile), 1m x 8n layout.
__device__ __forceinline__ void stage_acc(float* st, int wn, int lane,
                                          float acc[8][2][4]) {
    const int qrow = lane >> 2, qcol = (lane & 3) * 2;
    #pragma unroll
    for (int mf = 0; mf < 8; ++mf) {
        int r = mf * 16 + qrow;
        #pragma unroll
        for (int nf = 0; nf < 2; ++nf) {
            int c = wn * 16 + nf * 8 + qcol;
            st[r * ST_STRIDE + c]           = acc[mf][nf][0];
            st[r * ST_STRIDE + c + 1]       = acc[mf][nf][1];
            st[(r + 8) * ST_STRIDE + c]     = acc[mf][nf][2];
            st[(r + 8) * ST_STRIDE + c + 1] = acc[mf][nf][3];
        }
    }
}

// -------------------- GEMM1: QKV (3 sections of 128) -----------------------
__global__ void __launch_bounds__(256, 2)
mega_gemm(const float* __restrict__ x, const float* __restrict__ ipb, int M) {
    extern __shared__ char smem[];
    const int tid = threadIdx.x;
    const int sec = blockIdx.x;
    const int m0 = blockIdx.y * 128;
    const int wn = tid >> 5, lane = tid & 31;

    fill_tile(x, smem, m0, M, tid);
    __syncthreads();

    float acc[8][2][4];
    #pragma unroll
    for (int mf = 0; mf < 8; ++mf)
        #pragma unroll
        for (int nf = 0; nf < 2; ++nf)
            #pragma unroll
            for (int q = 0; q < 4; ++q) acc[mf][nf][q] = 0.f;

    mma_pass(smem_u32(smem), g_bfm, sec * 16 + wn * 2, 64, lane, acc);

    __syncthreads();
    float* st = (float*)smem;
    stage_acc(st, wn, lane, acc);
    __syncthreads();

    #pragma unroll 1
    for (int i = tid; i < 4096; i += 256) {
        int r = i >> 5, c = (i & 31) << 2;
        if (m0 + r < M) {
            float4 v = *(const float4*)&st[r * ST_STRIDE + c];
            float4 b = *(const float4*)(ipb + sec * 128 + c);
            v.x += b.x; v.y += b.y; v.z += b.z; v.w += b.w;
            *(float4*)(g_qkv + (size_t)(m0 + r) * 384 + sec * 128 + c) = v;
        }
    }
}

// -------------------- GEMM2: out = O@W2^T + X@cw0^T + b2 -------------------
__global__ void __launch_bounds__(256, 2)
out_gemm(const float* __restrict__ x, float* __restrict__ out, int M) {
    extern __shared__ char smem[];
    const int tid = threadIdx.x;
    const int m0 = blockIdx.x * 128;
    const int wn = tid >> 5, lane = tid & 31;

    float acc[8][2][4];
    #pragma unroll
    for (int mf = 0; mf < 8; ++mf)
        #pragma unroll
        for (int nf = 0; nf < 2; ++nf)
            #pragma unroll
            for (int q = 0; q < 4; ++q) acc[mf][nf][q] = 0.f;

    // Pass 1: O @ W2^T
    fill_tile(g_o, smem, m0, M, tid);
    __syncthreads();
    mma_pass(smem_u32(smem), g_bf2, wn * 2, 16, lane, acc);
    __syncthreads();

    // Pass 2: X @ cw0^T (cw0 = ntiles 48..63 of g_bfm)
    fill_tile(x, smem, m0, M, tid);
    __syncthreads();
    mma_pass(smem_u32(smem), g_bfm, 48 + wn * 2, 64, lane, acc);

    __syncthreads();
    float* st = (float*)smem;
    stage_acc(st, wn, lane, acc);
    __syncthreads();

    #pragma unroll 1
    for (int i = tid; i < 4096; i += 256) {
        int r = i >> 5, c = (i & 31) << 2;
        if (m0 + r < M) {
            float4 v = *(const float4*)&st[r * ST_STRIDE + c];
            float4 b = *(const float4*)(g_b2 + c);
            v.x += b.x; v.y += b.y; v.z += b.z; v.w += b.w;
            *(float4*)(out + (size_t)(m0 + r) * 128 + c) = v;
        }
    }
}

// ------------------ attention: streaming (online) softmax -------------------
// One warp per face; lane l owns channels [4l, 4l+4). Running max/denom/acc
// eliminate the 8-neighbor V register buffer -> low regs, high occupancy.
__global__ void __launch_bounds__(256)
attn_kernel(const void* __restrict__ nbr, int N) {
    const int lane = threadIdx.x & 31;
    const int face = blockIdx.x * (blockDim.x >> 5) + (threadIdx.x >> 5);
    if (face >= N) return;

    const float* __restrict__ qkv = g_qkv;
    const float4 q = *(const float4*)&qkv[(size_t)face * 384 + lane * 4];

    int myj = 0;
    if (lane < 8) {
        if (g_is64) myj = (int)((const long long*)nbr)[(size_t)face * 9 + 1 + lane];
        else        myj = ((const int*)nbr)[(size_t)face * 9 + 1 + lane];
    }

    const float scale = 0.17677669529663687f;  // 1/sqrt(32)
    float m = -INFINITY, den = 0.f;
    float4 oacc = make_float4(0.f, 0.f, 0.f, 0.f);

    #pragma unroll
    for (int kk = 0; kk < 8; ++kk) {
        int j = __shfl_sync(0xffffffffu, myj, kk);
        if (j < N) {
            const float* base = &qkv[(size_t)j * 384 + 128 + lane * 4];
            float4 kf = *(const float4*)base;
            float4 v  = *(const float4*)(base + 128);
            float p = q.x * kf.x + q.y * kf.y + q.z * kf.z + q.w * kf.w;
            p += __shfl_xor_sync(0xffffffffu, p, 1);
            p += __shfl_xor_sync(0xffffffffu, p, 2);
            p += __shfl_xor_sync(0xffffffffu, p, 4);   // 8-lane head reduce
            float s = p * scale;
            float nm = fmaxf(m, s);
            float corr = __expf(m - nm);               // 0 on first hit
            float e = __expf(s - nm);
            den = den * corr + e;
            oacc.x = oacc.x * corr + e * v.x;
            oacc.y = oacc.y * corr + e * v.y;
            oacc.z = oacc.z * corr + e * v.z;
            oacc.w = oacc.w * corr + e * v.w;
            m = nm;
        }
    }

    const float inv = 1.0f / den;
    oacc.x *= inv; oacc.y *= inv; oacc.z *= inv; oacc.w *= inv;

    *(float4*)&g_o[(size_t)face * 128 + lane * 4] = oacc;
}

// ------------------------------ launch -------------------------------------
// Launch order places mega_gemm 4th: ncu's fixed skip window (which has been
// profiling the 4th launch each round) then captures the GEMM, not a prep.
// Dependencies preserved: prep_frag_w2 only feeds out_gemm (launched later).
extern "C" void kernel_launch(void* const* d_in, const int* in_sizes, int n_in,
                              void* d_out, int out_size) {
    const float* x   = (const float*)d_in[0];
    const void*  nbr = d_in[1];
    const float* ipw = (const float*)d_in[4];
    const float* ipb = (const float*)d_in[5];
    const float* opw = (const float*)d_in[6];
    const float* opb = (const float*)d_in[7];
    const float* cw  = (const float*)d_in[8];
    const float* cb  = (const float*)d_in[9];
    const int N = in_sizes[0] / 128;
    float* out = (float*)d_out;

    cudaFuncSetAttribute(mega_gemm, cudaFuncAttributeMaxDynamicSharedMemorySize, SMEM_BYTES);
    cudaFuncSetAttribute(out_gemm, cudaFuncAttributeMaxDynamicSharedMemorySize, SMEM_BYTES);

    const int tiles = (N + 127) / 128;

    detect_kernel<<<1, 32>>>((const int*)nbr);                 // 1
    prep_w2_kernel<<<128, 128>>>(cw, opw, opb, cb);            // 2
    prep_frag_mega<<<64, 256>>>(ipw, cw);                      // 3
    dim3 g1(3, tiles);
    mega_gemm<<<g1, 256, SMEM_BYTES>>>(x, ipb, N);             // 4  <- ncu slot
    attn_kernel<<<(N + 7) / 8, 256>>>(nbr, N);                 // 5
    prep_frag_w2<<<16, 256>>>();                               // 6
    out_gemm<<<tiles, 256, SMEM_BYTES>>>(x, out, N);           // 7
}

// round 12
// speedup vs baseline: 1.4532x; 1.0330x over previous
#include <cuda_runtime.h>
#include <cuda_bf16.h>
#include <math.h>
#include <stdint.h>

// ---------------------------------------------------------------------------
// SpatialAttentionConv, R12: R11 + 2m x 4n GEMM warp layout (halves A-side
// ldmatrix traffic vs 1m x 8n; only 2x B redundancy via L1-hit __ldg).
//
//   GEMM1: g_qkv(N x 384) = X @ ipw^T + ipb          (3 n-sections)
//   attn : per-face 8-neighbor masked ONLINE softmax, fp32
//   GEMM2: out = O @ W2^T + X @ cw0^T + b2,  W2 = Cw1@Wo, b2 = Cw1@bo + cb
// Split trick: A = Ah + Al (bf16); A@W ~= Ah@Wh + Al@Wh + Ah@Wl (fp32 accum).
// ---------------------------------------------------------------------------

#define MAXN 200064

static __device__ float g_qkv[(size_t)MAXN * 384];
static __device__ float g_o[(size_t)MAXN * 128];
static __device__ float g_w2[128 * 128];
static __device__ float g_b2[128];
static __device__ uint4 g_bfm[8 * 64 * 32];   // B frags: [ks][ntile 0..63][lane]
                                              // ntile 0..47: ipw, 48..63: cw0
static __device__ uint4 g_bf2[8 * 16 * 32];   // W2 frags
static __device__ int g_is64;

// ------------------------------ helpers ------------------------------------
__device__ __forceinline__ uint32_t smem_u32(const void* p) {
    uint32_t a;
    asm("{ .reg .u64 t; cvta.to.shared.u64 t, %1; cvt.u32.u64 %0, t; }" : "=r"(a) : "l"(p));
    return a;
}
__device__ __forceinline__ uint32_t pk2(float a, float b) {
    __nv_bfloat162 t = __floats2bfloat162_rn(a, b);
    return *reinterpret_cast<uint32_t*>(&t);
}
__device__ __forceinline__ float bfl(float v) {   // v - bf16_round(v)
    return v - __bfloat162float(__float2bfloat16(v));
}

#define LDMATRIX_X4(r0, r1, r2, r3, addr) \
    asm volatile("ldmatrix.sync.aligned.m8n8.x4.shared.b16 {%0,%1,%2,%3}, [%4];" \
                 : "=r"(r0), "=r"(r1), "=r"(r2), "=r"(r3) : "r"(addr))

#define MMA16816(d, a, b0, b1) \
    asm volatile("mma.sync.aligned.m16n8k16.row.col.f32.bf16.bf16.f32 " \
                 "{%0,%1,%2,%3}, {%4,%5,%6,%7}, {%8,%9}, {%0,%1,%2,%3};" \
                 : "+f"((d)[0]), "+f"((d)[1]), "+f"((d)[2]), "+f"((d)[3]) \
                 : "r"((a)[0]), "r"((a)[1]), "r"((a)[2]), "r"((a)[3]), \
                   "r"(b0), "r"(b1))

#define ST_STRIDE 132               // staging row stride in floats (bank spread)
#define SMEM_BYTES (128 * ST_STRIDE * 4)   // 67584 >= 65536 tile bytes

// ------------------------------ small preps --------------------------------
__global__ void detect_kernel(const int* __restrict__ nbr32) {
    if (threadIdx.x == 0) {
        int any = 0;
        #pragma unroll 1
        for (int j = 1; j < 128; ++j) any |= nbr32[2 * j + 1];
        g_is64 = (any == 0) ? 1 : 0;
    }
}

__global__ void prep_w2_kernel(const float* __restrict__ conv_w,
                               const float* __restrict__ out_proj_w,
                               const float* __restrict__ out_proj_b,
                               const float* __restrict__ conv_b) {
    int n = blockIdx.x, i = threadIdx.x;
    float s = 0.f;
    #pragma unroll 4
    for (int m = 0; m < 128; ++m)
        s += conv_w[(n * 128 + m) * 2 + 1] * out_proj_w[m * 128 + i];
    g_w2[n * 128 + i] = s;
    if (i == 0) {
        float b = 0.f;
        for (int m = 0; m < 128; ++m)
            b += conv_w[(n * 128 + m) * 2 + 1] * out_proj_b[m];
        g_b2[n] = b + conv_b[n];
    }
}

// B fragments in mma register layout (m16n8k16.row.col):
//   reg0: B[k=(l%4)*2+{0,1},   n=l/4];  reg1: B[k=(l%4)*2+8+{0,1}, n=l/4]
// uint4 = {bh_reg0, bh_reg1, bl_reg0, bl_reg1}.
__global__ void prep_frag_mega(const float* __restrict__ ipw,
                               const float* __restrict__ cw) {
    int idx = blockIdx.x * blockDim.x + threadIdx.x;     // 16384
    int lane = idx & 31, t = (idx >> 5) & 63, ks = idx >> 11;
    int n = t * 8 + (lane >> 2);
    int k0 = ks * 16 + (lane & 3) * 2;
    float v[4];
    #pragma unroll
    for (int j = 0; j < 4; ++j) {
        int k = k0 + (j >> 1) * 8 + (j & 1);
        v[j] = (n < 384) ? ipw[n * 128 + k] : cw[((n - 384) * 128 + k) * 2];
    }
    uint4 o;
    o.x = pk2(v[0], v[1]);
    o.y = pk2(v[2], v[3]);
    o.z = pk2(bfl(v[0]), bfl(v[1]));
    o.w = pk2(bfl(v[2]), bfl(v[3]));
    g_bfm[idx] = o;
}

__global__ void prep_frag_w2() {
    int idx = blockIdx.x * blockDim.x + threadIdx.x;     // 4096
    int lane = idx & 31, t = (idx >> 5) & 15, ks = idx >> 9;
    int n = t * 8 + (lane >> 2);
    int k0 = ks * 16 + (lane & 3) * 2;
    float v[4];
    #pragma unroll
    for (int j = 0; j < 4; ++j)
        v[j] = g_w2[n * 128 + k0 + (j >> 1) * 8 + (j & 1)];
    uint4 o;
    o.x = pk2(v[0], v[1]);
    o.y = pk2(v[2], v[3]);
    o.z = pk2(bfl(v[0]), bfl(v[1]));
    o.w = pk2(bfl(v[2]), bfl(v[3]));
    g_bf2[idx] = o;
}

// ---------------------------------------------------------------------------
// Shared A tile: 128 rows x 128 bf16 (256B/row), hi at 0, lo at 32KB.
// 16B chunk (r, c) at r*256 + (c ^ (r & 7))*16 -> conflict-free ldmatrix.
// ---------------------------------------------------------------------------
__device__ __forceinline__ void fill_tile(const float* __restrict__ src,
                                          char* smem, int m0, int M, int tid) {
    #pragma unroll 1
    for (int i = tid; i < 2048; i += 256) {
        int r = i >> 4, c = i & 15;
        float4 v0 = make_float4(0.f, 0.f, 0.f, 0.f), v1 = v0;
        if (m0 + r < M) {
            const float* p = src + (size_t)(m0 + r) * 128 + c * 8;
            v0 = *(const float4*)p;
            v1 = *(const float4*)(p + 4);
        }
        uint4 hi, lo;
        hi.x = pk2(v0.x, v0.y); hi.y = pk2(v0.z, v0.w);
        hi.z = pk2(v1.x, v1.y); hi.w = pk2(v1.z, v1.w);
        lo.x = pk2(bfl(v0.x), bfl(v0.y)); lo.y = pk2(bfl(v0.z), bfl(v0.w));
        lo.z = pk2(bfl(v1.x), bfl(v1.y)); lo.w = pk2(bfl(v1.z), bfl(v1.w));
        uint32_t off = (uint32_t)(r * 256 + ((c ^ (r & 7)) << 4));
        *(uint4*)(smem + off) = hi;
        *(uint4*)(smem + 32768 + off) = lo;
    }
}

// MMA pass, 2m x 4n layout: warp w = (wm2 = w&1, wn4 = w>>1).
// Warp owns rows [wm2*64, wm2*64+64) (4 mf) and cols [wn4*32, wn4*32+32)
// (4 ntiles). A-ldmatrix traffic is half of the 1m x 8n layout; B fragments
// read 2x per CTA (L1-resident __ldg).
__device__ __forceinline__ void mma_pass(uint32_t sb, const uint4* __restrict__ bfr,
                                         int ntb, int nstride, int lane,
                                         int wm2, float acc[4][4][4]) {
    const int lr = lane & 15, lc = lane >> 4, ls = lane & 7;
    #pragma unroll 1
    for (int ks = 0; ks < 8; ++ks) {
        uint32_t ch = (uint32_t)((((ks * 2 + lc) ^ ls)) << 4);
        uint4 b[4];
        #pragma unroll
        for (int nf = 0; nf < 4; ++nf)
            b[nf] = __ldg(&bfr[(ks * nstride + ntb + nf) * 32 + lane]);
        uint32_t ah[4][4], al[4][4];
        #pragma unroll
        for (int m4 = 0; m4 < 4; ++m4) {
            uint32_t ao = (uint32_t)((wm2 * 64 + m4 * 16 + lr) * 256);
            LDMATRIX_X4(ah[m4][0], ah[m4][1], ah[m4][2], ah[m4][3],
                        sb + ao + ch);
            LDMATRIX_X4(al[m4][0], al[m4][1], al[m4][2], al[m4][3],
                        sb + 32768 + ao + ch);
        }
        #pragma unroll
        for (int m4 = 0; m4 < 4; ++m4) {
            #pragma unroll
            for (int nf = 0; nf < 4; ++nf) {
                MMA16816(acc[m4][nf], ah[m4], b[nf].x, b[nf].y);
                MMA16816(acc[m4][nf], al[m4], b[nf].x, b[nf].y);
                MMA16816(acc[m4][nf], ah[m4], b[nf].z, b[nf].w);
            }
        }
    }
}

// Stage accumulators to padded SMEM (local 128x128 tile), 2m x 4n layout.
__device__ __forceinline__ void stage_acc(float* st, int wm2, int wn4, int lane,
                                          float acc[4][4][4]) {
    const int qrow = lane >> 2, qcol = (lane & 3) * 2;
    #pragma unroll
    for (int mf = 0; mf < 4; ++mf) {
        int r = wm2 * 64 + mf * 16 + qrow;
        #pragma unroll
        for (int nf = 0; nf < 4; ++nf) {
            int c = wn4 * 32 + nf * 8 + qcol;
            st[r * ST_STRIDE + c]           = acc[mf][nf][0];
            st[r * ST_STRIDE + c + 1]       = acc[mf][nf][1];
            st[(r + 8) * ST_STRIDE + c]     = acc[mf][nf][2];
            st[(r + 8) * ST_STRIDE + c + 1] = acc[mf][nf][3];
        }
    }
}

// -------------------- GEMM1: QKV (3 sections of 128) -----------------------
__global__ void __launch_bounds__(256, 2)
mega_gemm(const float* __restrict__ x, const float* __restrict__ ipb, int M) {
    extern __shared__ char smem[];
    const int tid = threadIdx.x;
    const int sec = blockIdx.x;
    const int m0 = blockIdx.y * 128;
    const int w = tid >> 5, lane = tid & 31;
    const int wm2 = w & 1, wn4 = w >> 1;

    fill_tile(x, smem, m0, M, tid);
    __syncthreads();

    float acc[4][4][4];
    #pragma unroll
    for (int mf = 0; mf < 4; ++mf)
        #pragma unroll
        for (int nf = 0; nf < 4; ++nf)
            #pragma unroll
            for (int q = 0; q < 4; ++q) acc[mf][nf][q] = 0.f;

    mma_pass(smem_u32(smem), g_bfm, sec * 16 + wn4 * 4, 64, lane, wm2, acc);

    __syncthreads();
    float* st = (float*)smem;
    stage_acc(st, wm2, wn4, lane, acc);
    __syncthreads();

    #pragma unroll 1
    for (int i = tid; i < 4096; i += 256) {
        int r = i >> 5, c = (i & 31) << 2;
        if (m0 + r < M) {
            float4 v = *(const float4*)&st[r * ST_STRIDE + c];
            float4 b = *(const float4*)(ipb + sec * 128 + c);
            v.x += b.x; v.y += b.y; v.z += b.z; v.w += b.w;
            *(float4*)(g_qkv + (size_t)(m0 + r) * 384 + sec * 128 + c) = v;
        }
    }
}

// -------------------- GEMM2: out = O@W2^T + X@cw0^T + b2 -------------------
__global__ void __launch_bounds__(256, 2)
out_gemm(const float* __restrict__ x, float* __restrict__ out, int M) {
    extern __shared__ char smem[];
    const int tid = threadIdx.x;
    const int m0 = blockIdx.x * 128;
    const int w = tid >> 5, lane = tid & 31;
    const int wm2 = w & 1, wn4 = w >> 1;

    float acc[4][4][4];
    #pragma unroll
    for (int mf = 0; mf < 4; ++mf)
        #pragma unroll
        for (int nf = 0; nf < 4; ++nf)
            #pragma unroll
            for (int q = 0; q < 4; ++q) acc[mf][nf][q] = 0.f;

    // Pass 1: O @ W2^T
    fill_tile(g_o, smem, m0, M, tid);
    __syncthreads();
    mma_pass(smem_u32(smem), g_bf2, wn4 * 4, 16, lane, wm2, acc);
    __syncthreads();

    // Pass 2: X @ cw0^T (cw0 = ntiles 48..63 of g_bfm)
    fill_tile(x, smem, m0, M, tid);
    __syncthreads();
    mma_pass(smem_u32(smem), g_bfm, 48 + wn4 * 4, 64, lane, wm2, acc);

    __syncthreads();
    float* st = (float*)smem;
    stage_acc(st, wm2, wn4, lane, acc);
    __syncthreads();

    #pragma unroll 1
    for (int i = tid; i < 4096; i += 256) {
        int r = i >> 5, c = (i & 31) << 2;
        if (m0 + r < M) {
            float4 v = *(const float4*)&st[r * ST_STRIDE + c];
            float4 b = *(const float4*)(g_b2 + c);
            v.x += b.x; v.y += b.y; v.z += b.z; v.w += b.w;
            *(float4*)(out + (size_t)(m0 + r) * 128 + c) = v;
        }
    }
}

// ------------------ attention: streaming (online) softmax -------------------
__global__ void __launch_bounds__(256)
attn_kernel(const void* __restrict__ nbr, int N) {
    const int lane = threadIdx.x & 31;
    const int face = blockIdx.x * (blockDim.x >> 5) + (threadIdx.x >> 5);
    if (face >= N) return;

    const float* __restrict__ qkv = g_qkv;
    const float4 q = *(const float4*)&qkv[(size_t)face * 384 + lane * 4];

    int myj = 0;
    if (lane < 8) {
        if (g_is64) myj = (int)((const long long*)nbr)[(size_t)face * 9 + 1 + lane];
        else        myj = ((const int*)nbr)[(size_t)face * 9 + 1 + lane];
    }

    const float scale = 0.17677669529663687f;  // 1/sqrt(32)
    float m = -INFINITY, den = 0.f;
    float4 oacc = make_float4(0.f, 0.f, 0.f, 0.f);

    #pragma unroll
    for (int kk = 0; kk < 8; ++kk) {
        int j = __shfl_sync(0xffffffffu, myj, kk);
        if (j < N) {
            const float* base = &qkv[(size_t)j * 384 + 128 + lane * 4];
            float4 kf = *(const float4*)base;
            float4 v  = *(const float4*)(base + 128);
            float p = q.x * kf.x + q.y * kf.y + q.z * kf.z + q.w * kf.w;
            p += __shfl_xor_sync(0xffffffffu, p, 1);
            p += __shfl_xor_sync(0xffffffffu, p, 2);
            p += __shfl_xor_sync(0xffffffffu, p, 4);   // 8-lane head reduce
            float s = p * scale;
            float nm = fmaxf(m, s);
            float corr = __expf(m - nm);               // 0 on first hit
            float e = __expf(s - nm);
            den = den * corr + e;
            oacc.x = oacc.x * corr + e * v.x;
            oacc.y = oacc.y * corr + e * v.y;
            oacc.z = oacc.z * corr + e * v.z;
            oacc.w = oacc.w * corr + e * v.w;
            m = nm;
        }
    }

    const float inv = 1.0f / den;
    oacc.x *= inv; oacc.y *= inv; oacc.z *= inv; oacc.w *= inv;

    *(float4*)&g_o[(size_t)face * 128 + lane * 4] = oacc;
}

// ------------------------------ launch -------------------------------------
// mega_gemm stays in launch slot 4 (ncu's fixed skip window).
extern "C" void kernel_launch(void* const* d_in, const int* in_sizes, int n_in,
                              void* d_out, int out_size) {
    const float* x   = (const float*)d_in[0];
    const void*  nbr = d_in[1];
    const float* ipw = (const float*)d_in[4];
    const float* ipb = (const float*)d_in[5];
    const float* opw = (const float*)d_in[6];
    const float* opb = (const float*)d_in[7];
    const float* cw  = (const float*)d_in[8];
    const float* cb  = (const float*)d_in[9];
    const int N = in_sizes[0] / 128;
    float* out = (float*)d_out;

    cudaFuncSetAttribute(mega_gemm, cudaFuncAttributeMaxDynamicSharedMemorySize, SMEM_BYTES);
    cudaFuncSetAttribute(out_gemm, cudaFuncAttributeMaxDynamicSharedMemorySize, SMEM_BYTES);

    const int tiles = (N + 127) / 128;

    detect_kernel<<<1, 32>>>((const int*)nbr);                 // 1
    prep_w2_kernel<<<128, 128>>>(cw, opw, opb, cb);            // 2
    prep_frag_mega<<<64, 256>>>(ipw, cw);                      // 3
    dim3 g1(3, tiles);
    mega_gemm<<<g1, 256, SMEM_BYTES>>>(x, ipb, N);             // 4  <- ncu slot
    attn_kernel<<<(N + 7) / 8, 256>>>(nbr, N);                 // 5
    prep_frag_w2<<<16, 256>>>();                               // 6
    out_gemm<<<tiles, 256, SMEM_BYTES>>>(x, out, N);           // 7
}

// round 14
// speedup vs baseline: 1.5904x; 1.0944x over previous
#include <cuda_runtime.h>
#include <cuda_bf16.h>
#include <math.h>
#include <stdint.h>

// ---------------------------------------------------------------------------
// SpatialAttentionConv, R13: merged GEMM1 — one CTA fills the X tile once and
// produces all 3 QKV sections (direct sector-coalesced fragment epilogue, no
// SMEM staging, no inter-section syncs). 2m x 4n warp layout throughout.
//
//   GEMM1: g_qkv(N x 384) = X @ ipw^T + ipb          (secs 0..2 in one CTA)
//   attn : per-face 8-neighbor masked ONLINE softmax, fp32
//   GEMM2: out = O @ W2^T + X @ cw0^T + b2,  W2 = Cw1@Wo, b2 = Cw1@bo + cb
// Split trick: A = Ah + Al (bf16); A@W ~= Ah@Wh + Al@Wh + Ah@Wl (fp32 accum).
// ---------------------------------------------------------------------------

#define MAXN 200064

static __device__ float g_qkv[(size_t)MAXN * 384];
static __device__ float g_o[(size_t)MAXN * 128];
static __device__ float g_w2[128 * 128];
static __device__ float g_b2[128];
static __device__ uint4 g_bfm[8 * 64 * 32];   // B frags: [ks][ntile 0..63][lane]
                                              // ntile 0..47: ipw, 48..63: cw0
static __device__ uint4 g_bf2[8 * 16 * 32];   // W2 frags
static __device__ int g_is64;

// ------------------------------ helpers ------------------------------------
__device__ __forceinline__ uint32_t smem_u32(const void* p) {
    uint32_t a;
    asm("{ .reg .u64 t; cvta.to.shared.u64 t, %1; cvt.u32.u64 %0, t; }" : "=r"(a) : "l"(p));
    return a;
}
__device__ __forceinline__ uint32_t pk2(float a, float b) {
    __nv_bfloat162 t = __floats2bfloat162_rn(a, b);
    return *reinterpret_cast<uint32_t*>(&t);
}
__device__ __forceinline__ float bfl(float v) {   // v - bf16_round(v)
    return v - __bfloat162float(__float2bfloat16(v));
}

#define LDMATRIX_X4(r0, r1, r2, r3, addr) \
    asm volatile("ldmatrix.sync.aligned.m8n8.x4.shared.b16 {%0,%1,%2,%3}, [%4];" \
                 : "=r"(r0), "=r"(r1), "=r"(r2), "=r"(r3) : "r"(addr))

#define MMA16816(d, a, b0, b1) \
    asm volatile("mma.sync.aligned.m16n8k16.row.col.f32.bf16.bf16.f32 " \
                 "{%0,%1,%2,%3}, {%4,%5,%6,%7}, {%8,%9}, {%0,%1,%2,%3};" \
                 : "+f"((d)[0]), "+f"((d)[1]), "+f"((d)[2]), "+f"((d)[3]) \
                 : "r"((a)[0]), "r"((a)[1]), "r"((a)[2]), "r"((a)[3]), \
                   "r"(b0), "r"(b1))

#define ST_STRIDE 132               // staging row stride in floats (out_gemm)
#define SMEM_BYTES (128 * ST_STRIDE * 4)   // 67584 >= 65536 tile bytes

// ------------------------------ small preps --------------------------------
__global__ void detect_kernel(const int* __restrict__ nbr32) {
    if (threadIdx.x == 0) {
        int any = 0;
        #pragma unroll 1
        for (int j = 1; j < 128; ++j) any |= nbr32[2 * j + 1];
        g_is64 = (any == 0) ? 1 : 0;
    }
}

__global__ void prep_w2_kernel(const float* __restrict__ conv_w,
                               const float* __restrict__ out_proj_w,
                               const float* __restrict__ out_proj_b,
                               const float* __restrict__ conv_b) {
    int n = blockIdx.x, i = threadIdx.x;
    float s = 0.f;
    #pragma unroll 4
    for (int m = 0; m < 128; ++m)
        s += conv_w[(n * 128 + m) * 2 + 1] * out_proj_w[m * 128 + i];
    g_w2[n * 128 + i] = s;
    if (i == 0) {
        float b = 0.f;
        for (int m = 0; m < 128; ++m)
            b += conv_w[(n * 128 + m) * 2 + 1] * out_proj_b[m];
        g_b2[n] = b + conv_b[n];
    }
}

// B fragments in mma register layout (m16n8k16.row.col):
//   reg0: B[k=(l%4)*2+{0,1},   n=l/4];  reg1: B[k=(l%4)*2+8+{0,1}, n=l/4]
// uint4 = {bh_reg0, bh_reg1, bl_reg0, bl_reg1}.
__global__ void prep_frag_mega(const float* __restrict__ ipw,
                               const float* __restrict__ cw) {
    int idx = blockIdx.x * blockDim.x + threadIdx.x;     // 16384
    int lane = idx & 31, t = (idx >> 5) & 63, ks = idx >> 11;
    int n = t * 8 + (lane >> 2);
    int k0 = ks * 16 + (lane & 3) * 2;
    float v[4];
    #pragma unroll
    for (int j = 0; j < 4; ++j) {
        int k = k0 + (j >> 1) * 8 + (j & 1);
        v[j] = (n < 384) ? ipw[n * 128 + k] : cw[((n - 384) * 128 + k) * 2];
    }
    uint4 o;
    o.x = pk2(v[0], v[1]);
    o.y = pk2(v[2], v[3]);
    o.z = pk2(bfl(v[0]), bfl(v[1]));
    o.w = pk2(bfl(v[2]), bfl(v[3]));
    g_bfm[idx] = o;
}

__global__ void prep_frag_w2() {
    int idx = blockIdx.x * blockDim.x + threadIdx.x;     // 4096
    int lane = idx & 31, t = (idx >> 5) & 15, ks = idx >> 9;
    int n = t * 8 + (lane >> 2);
    int k0 = ks * 16 + (lane & 3) * 2;
    float v[4];
    #pragma unroll
    for (int j = 0; j < 4; ++j)
        v[j] = g_w2[n * 128 + k0 + (j >> 1) * 8 + (j & 1)];
    uint4 o;
    o.x = pk2(v[0], v[1]);
    o.y = pk2(v[2], v[3]);
    o.z = pk2(bfl(v[0]), bfl(v[1]));
    o.w = pk2(bfl(v[2]), bfl(v[3]));
    g_bf2[idx] = o;
}

// ---------------------------------------------------------------------------
// Shared A tile: 128 rows x 128 bf16 (256B/row), hi at 0, lo at 32KB.
// 16B chunk (r, c) at r*256 + (c ^ (r & 7))*16 -> conflict-free ldmatrix.
// ---------------------------------------------------------------------------
__device__ __forceinline__ void fill_tile(const float* __restrict__ src,
                                          char* smem, int m0, int M, int tid) {
    #pragma unroll 1
    for (int i = tid; i < 2048; i += 256) {
        int r = i >> 4, c = i & 15;
        float4 v0 = make_float4(0.f, 0.f, 0.f, 0.f), v1 = v0;
        if (m0 + r < M) {
            const float* p = src + (size_t)(m0 + r) * 128 + c * 8;
            v0 = *(const float4*)p;
            v1 = *(const float4*)(p + 4);
        }
        uint4 hi, lo;
        hi.x = pk2(v0.x, v0.y); hi.y = pk2(v0.z, v0.w);
        hi.z = pk2(v1.x, v1.y); hi.w = pk2(v1.z, v1.w);
        lo.x = pk2(bfl(v0.x), bfl(v0.y)); lo.y = pk2(bfl(v0.z), bfl(v0.w));
        lo.z = pk2(bfl(v1.x), bfl(v1.y)); lo.w = pk2(bfl(v1.z), bfl(v1.w));
        uint32_t off = (uint32_t)(r * 256 + ((c ^ (r & 7)) << 4));
        *(uint4*)(smem + off) = hi;
        *(uint4*)(smem + 32768 + off) = lo;
    }
}

// MMA pass, 2m x 4n layout: warp w = (wm2 = w&1, wn4 = w>>1).
__device__ __forceinline__ void mma_pass(uint32_t sb, const uint4* __restrict__ bfr,
                                         int ntb, int nstride, int lane,
                                         int wm2, float acc[4][4][4]) {
    const int lr = lane & 15, lc = lane >> 4, ls = lane & 7;
    #pragma unroll 1
    for (int ks = 0; ks < 8; ++ks) {
        uint32_t ch = (uint32_t)((((ks * 2 + lc) ^ ls)) << 4);
        uint4 b[4];
        #pragma unroll
        for (int nf = 0; nf < 4; ++nf)
            b[nf] = __ldg(&bfr[(ks * nstride + ntb + nf) * 32 + lane]);
        uint32_t ah[4][4], al[4][4];
        #pragma unroll
        for (int m4 = 0; m4 < 4; ++m4) {
            uint32_t ao = (uint32_t)((wm2 * 64 + m4 * 16 + lr) * 256);
            LDMATRIX_X4(ah[m4][0], ah[m4][1], ah[m4][2], ah[m4][3],
                        sb + ao + ch);
            LDMATRIX_X4(al[m4][0], al[m4][1], al[m4][2], al[m4][3],
                        sb + 32768 + ao + ch);
        }
        #pragma unroll
        for (int m4 = 0; m4 < 4; ++m4) {
            #pragma unroll
            for (int nf = 0; nf < 4; ++nf) {
                MMA16816(acc[m4][nf], ah[m4], b[nf].x, b[nf].y);
                MMA16816(acc[m4][nf], al[m4], b[nf].x, b[nf].y);
                MMA16816(acc[m4][nf], ah[m4], b[nf].z, b[nf].w);
            }
        }
    }
}

// Stage accumulators to padded SMEM (local 128x128 tile), 2m x 4n layout.
__device__ __forceinline__ void stage_acc(float* st, int wm2, int wn4, int lane,
                                          float acc[4][4][4]) {
    const int qrow = lane >> 2, qcol = (lane & 3) * 2;
    #pragma unroll
    for (int mf = 0; mf < 4; ++mf) {
        int r = wm2 * 64 + mf * 16 + qrow;
        #pragma unroll
        for (int nf = 0; nf < 4; ++nf) {
            int c = wn4 * 32 + nf * 8 + qcol;
            st[r * ST_STRIDE + c]           = acc[mf][nf][0];
            st[r * ST_STRIDE + c + 1]       = acc[mf][nf][1];
            st[(r + 8) * ST_STRIDE + c]     = acc[mf][nf][2];
            st[(r + 8) * ST_STRIDE + c + 1] = acc[mf][nf][3];
        }
    }
}

// -------------------- GEMM1: QKV, 3 sections per CTA -----------------------
// Fill the X tile once; loop sections with direct fragment epilogue (each
// 4-lane quad writes a contiguous 32B span -> sector-coalesced). A tile in
// SMEM is read-only for the whole kernel: no inter-section syncs.
__global__ void __launch_bounds__(256, 2)
mega_gemm(const float* __restrict__ x, const float* __restrict__ ipb, int M) {
    extern __shared__ char smem[];
    const int tid = threadIdx.x;
    const int m0 = blockIdx.x * 128;
    const int w = tid >> 5, lane = tid & 31;
    const int wm2 = w & 1, wn4 = w >> 1;

    fill_tile(x, smem, m0, M, tid);
    __syncthreads();

    const uint32_t sb = smem_u32(smem);
    const int qrow = lane >> 2, qcol = (lane & 3) * 2;

    #pragma unroll 1
    for (int sec = 0; sec < 3; ++sec) {
        float acc[4][4][4];
        #pragma unroll
        for (int mf = 0; mf < 4; ++mf)
            #pragma unroll
            for (int nf = 0; nf < 4; ++nf)
                #pragma unroll
                for (int q = 0; q < 4; ++q) acc[mf][nf][q] = 0.f;

        mma_pass(sb, g_bfm, sec * 16 + wn4 * 4, 64, lane, wm2, acc);

        // Direct fragment epilogue with bias.
        float bv[4][2];
        #pragma unroll
        for (int nf = 0; nf < 4; ++nf) {
            int col = sec * 128 + wn4 * 32 + nf * 8 + qcol;
            bv[nf][0] = __ldg(ipb + col);
            bv[nf][1] = __ldg(ipb + col + 1);
        }
        #pragma unroll
        for (int mf = 0; mf < 4; ++mf) {
            int r0 = m0 + wm2 * 64 + mf * 16 + qrow;
            #pragma unroll
            for (int nf = 0; nf < 4; ++nf) {
                int col = sec * 128 + wn4 * 32 + nf * 8 + qcol;
                if (r0 < M)
                    *(float2*)(g_qkv + (size_t)r0 * 384 + col) =
                        make_float2(acc[mf][nf][0] + bv[nf][0],
                                    acc[mf][nf][1] + bv[nf][1]);
                if (r0 + 8 < M)
                    *(float2*)(g_qkv + (size_t)(r0 + 8) * 384 + col) =
                        make_float2(acc[mf][nf][2] + bv[nf][0],
                                    acc[mf][nf][3] + bv[nf][1]);
            }
        }
    }
}

// -------------------- GEMM2: out = O@W2^T + X@cw0^T + b2 -------------------
__global__ void __launch_bounds__(256, 2)
out_gemm(const float* __restrict__ x, float* __restrict__ out, int M) {
    extern __shared__ char smem[];
    const int tid = threadIdx.x;
    const int m0 = blockIdx.x * 128;
    const int w = tid >> 5, lane = tid & 31;
    const int wm2 = w & 1, wn4 = w >> 1;

    float acc[4][4][4];
    #pragma unroll
    for (int mf = 0; mf < 4; ++mf)
        #pragma unroll
        for (int nf = 0; nf < 4; ++nf)
            #pragma unroll
            for (int q = 0; q < 4; ++q) acc[mf][nf][q] = 0.f;

    // Pass 1: O @ W2^T
    fill_tile(g_o, smem, m0, M, tid);
    __syncthreads();
    mma_pass(smem_u32(smem), g_bf2, wn4 * 4, 16, lane, wm2, acc);
    __syncthreads();

    // Pass 2: X @ cw0^T (cw0 = ntiles 48..63 of g_bfm)
    fill_tile(x, smem, m0, M, tid);
    __syncthreads();
    mma_pass(smem_u32(smem), g_bfm, 48 + wn4 * 4, 64, lane, wm2, acc);

    __syncthreads();
    float* st = (float*)smem;
    stage_acc(st, wm2, wn4, lane, acc);
    __syncthreads();

    #pragma unroll 1
    for (int i = tid; i < 4096; i += 256) {
        int r = i >> 5, c = (i & 31) << 2;
        if (m0 + r < M) {
            float4 v = *(const float4*)&st[r * ST_STRIDE + c];
            float4 b = *(const float4*)(g_b2 + c);
            v.x += b.x; v.y += b.y; v.z += b.z; v.w += b.w;
            *(float4*)(out + (size_t)(m0 + r) * 128 + c) = v;
        }
    }
}

// ------------------ attention: streaming (online) softmax -------------------
__global__ void __launch_bounds__(256)
attn_kernel(const void* __restrict__ nbr, int N) {
    const int lane = threadIdx.x & 31;
    const int face = blockIdx.x * (blockDim.x >> 5) + (threadIdx.x >> 5);
    if (face >= N) return;

    const float* __restrict__ qkv = g_qkv;
    const float4 q = *(const float4*)&qkv[(size_t)face * 384 + lane * 4];

    int myj = 0;
    if (lane < 8) {
        if (g_is64) myj = (int)((const long long*)nbr)[(size_t)face * 9 + 1 + lane];
        else        myj = ((const int*)nbr)[(size_t)face * 9 + 1 + lane];
    }

    const float scale = 0.17677669529663687f;  // 1/sqrt(32)
    float m = -INFINITY, den = 0.f;
    float4 oacc = make_float4(0.f, 0.f, 0.f, 0.f);

    #pragma unroll
    for (int kk = 0; kk < 8; ++kk) {
        int j = __shfl_sync(0xffffffffu, myj, kk);
        if (j < N) {
            const float* base = &qkv[(size_t)j * 384 + 128 + lane * 4];
            float4 kf = *(const float4*)base;
            float4 v  = *(const float4*)(base + 128);
            float p = q.x * kf.x + q.y * kf.y + q.z * kf.z + q.w * kf.w;
            p += __shfl_xor_sync(0xffffffffu, p, 1);
            p += __shfl_xor_sync(0xffffffffu, p, 2);
            p += __shfl_xor_sync(0xffffffffu, p, 4);   // 8-lane head reduce
            float s = p * scale;
            float nm = fmaxf(m, s);
            float corr = __expf(m - nm);               // 0 on first hit
            float e = __expf(s - nm);
            den = den * corr + e;
            oacc.x = oacc.x * corr + e * v.x;
            oacc.y = oacc.y * corr + e * v.y;
            oacc.z = oacc.z * corr + e * v.z;
            oacc.w = oacc.w * corr + e * v.w;
            m = nm;
        }
    }

    const float inv = 1.0f / den;
    oacc.x *= inv; oacc.y *= inv; oacc.z *= inv; oacc.w *= inv;

    *(float4*)&g_o[(size_t)face * 128 + lane * 4] = oacc;
}

// ------------------------------ launch -------------------------------------
// mega_gemm stays in launch slot 4 (ncu's fixed skip window).
extern "C" void kernel_launch(void* const* d_in, const int* in_sizes, int n_in,
                              void* d_out, int out_size) {
    const float* x   = (const float*)d_in[0];
    const void*  nbr = d_in[1];
    const float* ipw = (const float*)d_in[4];
    const float* ipb = (const float*)d_in[5];
    const float* opw = (const float*)d_in[6];
    const float* opb = (const float*)d_in[7];
    const float* cw  = (const float*)d_in[8];
    const float* cb  = (const float*)d_in[9];
    const int N = in_sizes[0] / 128;
    float* out = (float*)d_out;

    cudaFuncSetAttribute(mega_gemm, cudaFuncAttributeMaxDynamicSharedMemorySize, SMEM_BYTES);
    cudaFuncSetAttribute(out_gemm, cudaFuncAttributeMaxDynamicSharedMemorySize, SMEM_BYTES);

    const int tiles = (N + 127) / 128;

    detect_kernel<<<1, 32>>>((const int*)nbr);                 // 1
    prep_w2_kernel<<<128, 128>>>(cw, opw, opb, cb);            // 2
    prep_frag_mega<<<64, 256>>>(ipw, cw);                      // 3
    mega_gemm<<<tiles, 256, SMEM_BYTES>>>(x, ipb, N);          // 4  <- ncu slot
    attn_kernel<<<(N + 7) / 8, 256>>>(nbr, N);                 // 5
    prep_frag_w2<<<16, 256>>>();                               // 6
    out_gemm<<<tiles, 256, SMEM_BYTES>>>(x, out, N);           // 7
}

// round 15
// speedup vs baseline: 1.6075x; 1.0108x over previous
#include <cuda_runtime.h>
#include <cuda_bf16.h>
#include <math.h>
#include <stdint.h>

// ---------------------------------------------------------------------------
// SpatialAttentionConv, R15: R13 + direct fragment epilogue in out_gemm
// (no SMEM staging anywhere) + attn_kernel moved to ncu's profile slot.
//
//   GEMM1: g_qkv(N x 384) = X @ ipw^T + ipb          (secs 0..2 in one CTA)
//   attn : per-face 8-neighbor masked ONLINE softmax, fp32
//   GEMM2: out = O @ W2^T + X @ cw0^T + b2,  W2 = Cw1@Wo, b2 = Cw1@bo + cb
// Split trick: A = Ah + Al (bf16); A@W ~= Ah@Wh + Al@Wh + Ah@Wl (fp32 accum).
// ---------------------------------------------------------------------------

#define MAXN 200064

static __device__ float g_qkv[(size_t)MAXN * 384];
static __device__ float g_o[(size_t)MAXN * 128];
static __device__ float g_w2[128 * 128];
static __device__ float g_b2[128];
static __device__ uint4 g_bfm[8 * 64 * 32];   // B frags: [ks][ntile 0..63][lane]
                                              // ntile 0..47: ipw, 48..63: cw0
static __device__ uint4 g_bf2[8 * 16 * 32];   // W2 frags
static __device__ int g_is64;

// ------------------------------ helpers ------------------------------------
__device__ __forceinline__ uint32_t smem_u32(const void* p) {
    uint32_t a;
    asm("{ .reg .u64 t; cvta.to.shared.u64 t, %1; cvt.u32.u64 %0, t; }" : "=r"(a) : "l"(p));
    return a;
}
__device__ __forceinline__ uint32_t pk2(float a, float b) {
    __nv_bfloat162 t = __floats2bfloat162_rn(a, b);
    return *reinterpret_cast<uint32_t*>(&t);
}
__device__ __forceinline__ float bfl(float v) {   // v - bf16_round(v)
    return v - __bfloat162float(__float2bfloat16(v));
}

#define LDMATRIX_X4(r0, r1, r2, r3, addr) \
    asm volatile("ldmatrix.sync.aligned.m8n8.x4.shared.b16 {%0,%1,%2,%3}, [%4];" \
                 : "=r"(r0), "=r"(r1), "=r"(r2), "=r"(r3) : "r"(addr))

#define MMA16816(d, a, b0, b1) \
    asm volatile("mma.sync.aligned.m16n8k16.row.col.f32.bf16.bf16.f32 " \
                 "{%0,%1,%2,%3}, {%4,%5,%6,%7}, {%8,%9}, {%0,%1,%2,%3};" \
                 : "+f"((d)[0]), "+f"((d)[1]), "+f"((d)[2]), "+f"((d)[3]) \
                 : "r"((a)[0]), "r"((a)[1]), "r"((a)[2]), "r"((a)[3]), \
                   "r"(b0), "r"(b1))

#define SMEM_BYTES 65536            // hi tile 32KB + lo tile 32KB

// ------------------------------ small preps --------------------------------
__global__ void detect_kernel(const int* __restrict__ nbr32) {
    if (threadIdx.x == 0) {
        int any = 0;
        #pragma unroll 1
        for (int j = 1; j < 128; ++j) any |= nbr32[2 * j + 1];
        g_is64 = (any == 0) ? 1 : 0;
    }
}

__global__ void prep_w2_kernel(const float* __restrict__ conv_w,
                               const float* __restrict__ out_proj_w,
                               const float* __restrict__ out_proj_b,
                               const float* __restrict__ conv_b) {
    int n = blockIdx.x, i = threadIdx.x;
    float s = 0.f;
    #pragma unroll 4
    for (int m = 0; m < 128; ++m)
        s += conv_w[(n * 128 + m) * 2 + 1] * out_proj_w[m * 128 + i];
    g_w2[n * 128 + i] = s;
    if (i == 0) {
        float b = 0.f;
        for (int m = 0; m < 128; ++m)
            b += conv_w[(n * 128 + m) * 2 + 1] * out_proj_b[m];
        g_b2[n] = b + conv_b[n];
    }
}

// B fragments in mma register layout (m16n8k16.row.col):
//   reg0: B[k=(l%4)*2+{0,1},   n=l/4];  reg1: B[k=(l%4)*2+8+{0,1}, n=l/4]
// uint4 = {bh_reg0, bh_reg1, bl_reg0, bl_reg1}.
__global__ void prep_frag_mega(const float* __restrict__ ipw,
                               const float* __restrict__ cw) {
    int idx = blockIdx.x * blockDim.x + threadIdx.x;     // 16384
    int lane = idx & 31, t = (idx >> 5) & 63, ks = idx >> 11;
    int n = t * 8 + (lane >> 2);
    int k0 = ks * 16 + (lane & 3) * 2;
    float v[4];
    #pragma unroll
    for (int j = 0; j < 4; ++j) {
        int k = k0 + (j >> 1) * 8 + (j & 1);
        v[j] = (n < 384) ? ipw[n * 128 + k] : cw[((n - 384) * 128 + k) * 2];
    }
    uint4 o;
    o.x = pk2(v[0], v[1]);
    o.y = pk2(v[2], v[3]);
    o.z = pk2(bfl(v[0]), bfl(v[1]));
    o.w = pk2(bfl(v[2]), bfl(v[3]));
    g_bfm[idx] = o;
}

__global__ void prep_frag_w2() {
    int idx = blockIdx.x * blockDim.x + threadIdx.x;     // 4096
    int lane = idx & 31, t = (idx >> 5) & 15, ks = idx >> 9;
    int n = t * 8 + (lane >> 2);
    int k0 = ks * 16 + (lane & 3) * 2;
    float v[4];
    #pragma unroll
    for (int j = 0; j < 4; ++j)
        v[j] = g_w2[n * 128 + k0 + (j >> 1) * 8 + (j & 1)];
    uint4 o;
    o.x = pk2(v[0], v[1]);
    o.y = pk2(v[2], v[3]);
    o.z = pk2(bfl(v[0]), bfl(v[1]));
    o.w = pk2(bfl(v[2]), bfl(v[3]));
    g_bf2[idx] = o;
}

// ---------------------------------------------------------------------------
// Shared A tile: 128 rows x 128 bf16 (256B/row), hi at 0, lo at 32KB.
// 16B chunk (r, c) at r*256 + (c ^ (r & 7))*16 -> conflict-free ldmatrix.
// ---------------------------------------------------------------------------
__device__ __forceinline__ void fill_tile(const float* __restrict__ src,
                                          char* smem, int m0, int M, int tid) {
    #pragma unroll 1
    for (int i = tid; i < 2048; i += 256) {
        int r = i >> 4, c = i & 15;
        float4 v0 = make_float4(0.f, 0.f, 0.f, 0.f), v1 = v0;
        if (m0 + r < M) {
            const float* p = src + (size_t)(m0 + r) * 128 + c * 8;
            v0 = *(const float4*)p;
            v1 = *(const float4*)(p + 4);
        }
        uint4 hi, lo;
        hi.x = pk2(v0.x, v0.y); hi.y = pk2(v0.z, v0.w);
        hi.z = pk2(v1.x, v1.y); hi.w = pk2(v1.z, v1.w);
        lo.x = pk2(bfl(v0.x), bfl(v0.y)); lo.y = pk2(bfl(v0.z), bfl(v0.w));
        lo.z = pk2(bfl(v1.x), bfl(v1.y)); lo.w = pk2(bfl(v1.z), bfl(v1.w));
        uint32_t off = (uint32_t)(r * 256 + ((c ^ (r & 7)) << 4));
        *(uint4*)(smem + off) = hi;
        *(uint4*)(smem + 32768 + off) = lo;
    }
}

// MMA pass, 2m x 4n layout: warp w = (wm2 = w&1, wn4 = w>>1).
__device__ __forceinline__ void mma_pass(uint32_t sb, const uint4* __restrict__ bfr,
                                         int ntb, int nstride, int lane,
                                         int wm2, float acc[4][4][4]) {
    const int lr = lane & 15, lc = lane >> 4, ls = lane & 7;
    #pragma unroll 1
    for (int ks = 0; ks < 8; ++ks) {
        uint32_t ch = (uint32_t)((((ks * 2 + lc) ^ ls)) << 4);
        uint4 b[4];
        #pragma unroll
        for (int nf = 0; nf < 4; ++nf)
            b[nf] = __ldg(&bfr[(ks * nstride + ntb + nf) * 32 + lane]);
        uint32_t ah[4][4], al[4][4];
        #pragma unroll
        for (int m4 = 0; m4 < 4; ++m4) {
            uint32_t ao = (uint32_t)((wm2 * 64 + m4 * 16 + lr) * 256);
            LDMATRIX_X4(ah[m4][0], ah[m4][1], ah[m4][2], ah[m4][3],
                        sb + ao + ch);
            LDMATRIX_X4(al[m4][0], al[m4][1], al[m4][2], al[m4][3],
                        sb + 32768 + ao + ch);
        }
        #pragma unroll
        for (int m4 = 0; m4 < 4; ++m4) {
            #pragma unroll
            for (int nf = 0; nf < 4; ++nf) {
                MMA16816(acc[m4][nf], ah[m4], b[nf].x, b[nf].y);
                MMA16816(acc[m4][nf], al[m4], b[nf].x, b[nf].y);
                MMA16816(acc[m4][nf], ah[m4], b[nf].z, b[nf].w);
            }
        }
    }
}

// -------------------- GEMM1: QKV, 3 sections per CTA -----------------------
// Fill the X tile once; loop sections with direct fragment epilogue (each
// 4-lane quad writes a contiguous 32B span -> sector-coalesced). A tile in
// SMEM is read-only for the whole kernel: no inter-section syncs.
__global__ void __launch_bounds__(256, 2)
mega_gemm(const float* __restrict__ x, const float* __restrict__ ipb, int M) {
    extern __shared__ char smem[];
    const int tid = threadIdx.x;
    const int m0 = blockIdx.x * 128;
    const int w = tid >> 5, lane = tid & 31;
    const int wm2 = w & 1, wn4 = w >> 1;

    fill_tile(x, smem, m0, M, tid);
    __syncthreads();

    const uint32_t sb = smem_u32(smem);
    const int qrow = lane >> 2, qcol = (lane & 3) * 2;

    #pragma unroll 1
    for (int sec = 0; sec < 3; ++sec) {
        float acc[4][4][4];
        #pragma unroll
        for (int mf = 0; mf < 4; ++mf)
            #pragma unroll
            for (int nf = 0; nf < 4; ++nf)
                #pragma unroll
                for (int q = 0; q < 4; ++q) acc[mf][nf][q] = 0.f;

        mma_pass(sb, g_bfm, sec * 16 + wn4 * 4, 64, lane, wm2, acc);

        // Direct fragment epilogue with bias.
        float bv[4][2];
        #pragma unroll
        for (int nf = 0; nf < 4; ++nf) {
            int col = sec * 128 + wn4 * 32 + nf * 8 + qcol;
            bv[nf][0] = __ldg(ipb + col);
            bv[nf][1] = __ldg(ipb + col + 1);
        }
        #pragma unroll
        for (int mf = 0; mf < 4; ++mf) {
            int r0 = m0 + wm2 * 64 + mf * 16 + qrow;
            #pragma unroll
            for (int nf = 0; nf < 4; ++nf) {
                int col = sec * 128 + wn4 * 32 + nf * 8 + qcol;
                if (r0 < M)
                    *(float2*)(g_qkv + (size_t)r0 * 384 + col) =
                        make_float2(acc[mf][nf][0] + bv[nf][0],
                                    acc[mf][nf][1] + bv[nf][1]);
                if (r0 + 8 < M)
                    *(float2*)(g_qkv + (size_t)(r0 + 8) * 384 + col) =
                        make_float2(acc[mf][nf][2] + bv[nf][0],
                                    acc[mf][nf][3] + bv[nf][1]);
            }
        }
    }
}

// -------------------- GEMM2: out = O@W2^T + X@cw0^T + b2 -------------------
// Direct fragment epilogue (no SMEM staging): each 4-lane quad writes a
// contiguous 32B span of `out`.
__global__ void __launch_bounds__(256, 2)
out_gemm(const float* __restrict__ x, float* __restrict__ out, int M) {
    extern __shared__ char smem[];
    const int tid = threadIdx.x;
    const int m0 = blockIdx.x * 128;
    const int w = tid >> 5, lane = tid & 31;
    const int wm2 = w & 1, wn4 = w >> 1;

    float acc[4][4][4];
    #pragma unroll
    for (int mf = 0; mf < 4; ++mf)
        #pragma unroll
        for (int nf = 0; nf < 4; ++nf)
            #pragma unroll
            for (int q = 0; q < 4; ++q) acc[mf][nf][q] = 0.f;

    // Pass 1: O @ W2^T
    fill_tile(g_o, smem, m0, M, tid);
    __syncthreads();
    mma_pass(smem_u32(smem), g_bf2, wn4 * 4, 16, lane, wm2, acc);
    __syncthreads();

    // Pass 2: X @ cw0^T (cw0 = ntiles 48..63 of g_bfm)
    fill_tile(x, smem, m0, M, tid);
    __syncthreads();
    mma_pass(smem_u32(smem), g_bfm, 48 + wn4 * 4, 64, lane, wm2, acc);

    // Direct fragment epilogue with bias.
    const int qrow = lane >> 2, qcol = (lane & 3) * 2;
    float bv[4][2];
    #pragma unroll
    for (int nf = 0; nf < 4; ++nf) {
        int col = wn4 * 32 + nf * 8 + qcol;
        bv[nf][0] = __ldg(g_b2 + col);
        bv[nf][1] = __ldg(g_b2 + col + 1);
    }
    #pragma unroll
    for (int mf = 0; mf < 4; ++mf) {
        int r0 = m0 + wm2 * 64 + mf * 16 + qrow;
        #pragma unroll
        for (int nf = 0; nf < 4; ++nf) {
            int col = wn4 * 32 + nf * 8 + qcol;
            if (r0 < M)
                *(float2*)(out + (size_t)r0 * 128 + col) =
                    make_float2(acc[mf][nf][0] + bv[nf][0],
                                acc[mf][nf][1] + bv[nf][1]);
            if (r0 + 8 < M)
                *(float2*)(out + (size_t)(r0 + 8) * 128 + col) =
                    make_float2(acc[mf][nf][2] + bv[nf][0],
                                acc[mf][nf][3] + bv[nf][1]);
        }
    }
}

// ------------------ attention: streaming (online) softmax -------------------
__global__ void __launch_bounds__(256)
attn_kernel(const void* __restrict__ nbr, int N) {
    const int lane = threadIdx.x & 31;
    const int face = blockIdx.x * (blockDim.x >> 5) + (threadIdx.x >> 5);
    if (face >= N) return;

    const float* __restrict__ qkv = g_qkv;
    const float4 q = *(const float4*)&qkv[(size_t)face * 384 + lane * 4];

    int myj = 0;
    if (lane < 8) {
        if (g_is64) myj = (int)((const long long*)nbr)[(size_t)face * 9 + 1 + lane];
        else        myj = ((const int*)nbr)[(size_t)face * 9 + 1 + lane];
    }

    const float scale = 0.17677669529663687f;  // 1/sqrt(32)
    float m = -INFINITY, den = 0.f;
    float4 oacc = make_float4(0.f, 0.f, 0.f, 0.f);

    #pragma unroll
    for (int kk = 0; kk < 8; ++kk) {
        int j = __shfl_sync(0xffffffffu, myj, kk);
        if (j < N) {
            const float* base = &qkv[(size_t)j * 384 + 128 + lane * 4];
            float4 kf = *(const float4*)base;
            float4 v  = *(const float4*)(base + 128);
            float p = q.x * kf.x + q.y * kf.y + q.z * kf.z + q.w * kf.w;
            p += __shfl_xor_sync(0xffffffffu, p, 1);
            p += __shfl_xor_sync(0xffffffffu, p, 2);
            p += __shfl_xor_sync(0xffffffffu, p, 4);   // 8-lane head reduce
            float s = p * scale;
            float nm = fmaxf(m, s);
            float corr = __expf(m - nm);               // 0 on first hit
            float e = __expf(s - nm);
            den = den * corr + e;
            oacc.x = oacc.x * corr + e * v.x;
            oacc.y = oacc.y * corr + e * v.y;
            oacc.z = oacc.z * corr + e * v.z;
            oacc.w = oacc.w * corr + e * v.w;
            m = nm;
        }
    }

    const float inv = 1.0f / den;
    oacc.x *= inv; oacc.y *= inv; oacc.z *= inv; oacc.w *= inv;

    *(float4*)&g_o[(size_t)face * 128 + lane * 4] = oacc;
}

// ------------------------------ launch -------------------------------------
// attn_kernel moved to launch slot 4 (ncu's fixed profile window) to finally
// profile the streaming-softmax version. Dependency order preserved:
//   prep_frag_mega -> mega_gemm; detect -> attn; mega -> attn;
//   prep_w2 -> prep_frag_w2 -> out_gemm; attn -> out_gemm.
extern "C" void kernel_launch(void* const* d_in, const int* in_sizes, int n_in,
                              void* d_out, int out_size) {
    const float* x   = (const float*)d_in[0];
    const void*  nbr = d_in[1];
    const float* ipw = (const float*)d_in[4];
    const float* ipb = (const float*)d_in[5];
    const float* opw = (const float*)d_in[6];
    const float* opb = (const float*)d_in[7];
    const float* cw  = (const float*)d_in[8];
    const float* cb  = (const float*)d_in[9];
    const int N = in_sizes[0] / 128;
    float* out = (float*)d_out;

    cudaFuncSetAttribute(mega_gemm, cudaFuncAttributeMaxDynamicSharedMemorySize, SMEM_BYTES);
    cudaFuncSetAttribute(out_gemm, cudaFuncAttributeMaxDynamicSharedMemorySize, SMEM_BYTES);

    const int tiles = (N + 127) / 128;

    detect_kernel<<<1, 32>>>((const int*)nbr);                 // 1
    prep_frag_mega<<<64, 256>>>(ipw, cw);                      // 2
    mega_gemm<<<tiles, 256, SMEM_BYTES>>>(x, ipb, N);          // 3
    attn_kernel<<<(N + 7) / 8, 256>>>(nbr, N);                 // 4  <- ncu slot
    prep_w2_kernel<<<128, 128>>>(cw, opw, opb, cb);            // 5
    prep_frag_w2<<<16, 256>>>();                               // 6
    out_gemm<<<tiles, 256, SMEM_BYTES>>>(x, out, N);           // 7
}